// round 3
// baseline (speedup 1.0000x reference)
#include <cuda_runtime.h>
#include <math.h>

// ---------------- constants ----------------
constexpr int D_  = 1024;
constexpr int S_  = 1024;
constexpr int N_  = 16;
constexpr int E_  = 16;
constexpr int T_  = 512;
constexpr int BT  = 1024;   // B*T
constexpr float EPS_ = 1e-8f;

// ---------------- scratch (static device globals; no allocations) ----------------
__device__ float g_P    [BT * 2048];
__device__ float g_XI   [BT * 2048];
__device__ float g_XR   [BT * D_];
__device__ float g_glcm [BT * D_];
__device__ float g_delta[BT * S_];
__device__ float g_Bmat [BT * S_ * N_];
__device__ float g_Cmat [BT * S_ * N_];
__device__ float g_y    [BT * S_];
__device__ float g_yo   [BT * D_];
__device__ float g_s6   [BT * D_];
__device__ float g_g1   [BT * D_];
__device__ float g_g2   [BT * D_];
__device__ float g_h    [BT * D_];
__device__ float g_e1   [2 * BT * 4096];
__device__ float g_e2   [2 * BT * D_];
__device__ int   g_cnt  [E_];
__device__ int   g_list [E_ * BT];
__device__ float g_w    [2 * BT];

// ---------------- helpers ----------------
__device__ __forceinline__ unsigned long long pack2(float x, float y) {
    unsigned long long r;
    asm("mov.b64 %0, {%1,%2};" : "=l"(r) : "f"(x), "f"(y));
    return r;
}
__device__ __forceinline__ void fma2(unsigned long long& d, unsigned long long a, unsigned long long b) {
    asm("fma.rn.f32x2 %0, %1, %2, %0;" : "+l"(d) : "l"(a), "l"(b));
}
__device__ __forceinline__ float2 unpack2(unsigned long long v) {
    float2 r;
    asm("mov.b64 {%0,%1}, %2;" : "=f"(r.x), "=f"(r.y) : "l"(v));
    return r;
}
__device__ __forceinline__ float sigmoidf_(float x) { return 1.f / (1.f + expf(-x)); }

__device__ __forceinline__ float block_sum256(float v) {
    __shared__ float sh[8];
    int lane = threadIdx.x & 31, w = threadIdx.x >> 5;
#pragma unroll
    for (int o = 16; o; o >>= 1) v += __shfl_xor_sync(0xffffffffu, v, o);
    if (lane == 0) sh[w] = v;
    __syncthreads();
    float s = 0.f;
#pragma unroll
    for (int i = 0; i < 8; i++) s += sh[i];
    return s;
}

// ---------------- generic SGEMM: C[M,N] = A[M,K] @ W[K,N] + bias, epilogue ----------------
// EPI: 0 = none, 1 = softplus, 2 = sigmoid
// Tiles: 128x128x16, 256 threads, 8x8 per thread, f32x2 packed FMA.
// All dims are multiples of tile sizes (checked at call sites), no guards needed.
template <int EPI>
__global__ __launch_bounds__(256)
void sgemm_kernel(const float* __restrict__ A, const float* __restrict__ W,
                  const float* __restrict__ bias, float* __restrict__ C,
                  int M, int N, int K) {
    __shared__ float As[16][128];
    __shared__ float Bs[16][132];

    const int tid = threadIdx.x;
    const int tx = tid & 15, ty = tid >> 4;
    const int aRowBase = blockIdx.y * 128;
    const int bcol     = blockIdx.x * 128;

    unsigned long long acc2[8][4] = {};

    for (int k0 = 0; k0 < K; k0 += 16) {
        // load A tile (128x16) transposed into As[k][m]
#pragma unroll
        for (int i = 0; i < 2; i++) {
            int v = tid * 2 + i;          // float4 idx 0..511
            int r = v >> 2, c4 = v & 3;
            float4 t = *(const float4*)(A + (size_t)(aRowBase + r) * K + k0 + c4 * 4);
            As[c4 * 4 + 0][r] = t.x;
            As[c4 * 4 + 1][r] = t.y;
            As[c4 * 4 + 2][r] = t.z;
            As[c4 * 4 + 3][r] = t.w;
        }
        // load B tile (16x128)
#pragma unroll
        for (int i = 0; i < 2; i++) {
            int v = tid * 2 + i;
            int r = v >> 5, c4 = v & 31;
            *(float4*)(&Bs[r][c4 * 4]) = *(const float4*)(W + (size_t)(k0 + r) * N + bcol + c4 * 4);
        }
        __syncthreads();
#pragma unroll
        for (int kk = 0; kk < 16; kk++) {
            float4 alo = *(const float4*)&As[kk][ty * 8];
            float4 ahi = *(const float4*)&As[kk][ty * 8 + 4];
            const unsigned long long* bp = (const unsigned long long*)&Bs[kk][tx * 8];
            unsigned long long b2[4];
            b2[0] = bp[0]; b2[1] = bp[1]; b2[2] = bp[2]; b2[3] = bp[3];
            float av[8] = {alo.x, alo.y, alo.z, alo.w, ahi.x, ahi.y, ahi.z, ahi.w};
#pragma unroll
            for (int i = 0; i < 8; i++) {
                unsigned long long a2 = pack2(av[i], av[i]);
#pragma unroll
                for (int jp = 0; jp < 4; jp++) fma2(acc2[i][jp], a2, b2[jp]);
            }
        }
        __syncthreads();
    }

#pragma unroll
    for (int i = 0; i < 8; i++) {
        size_t row = (size_t)(aRowBase + ty * 8 + i);
#pragma unroll
        for (int jp = 0; jp < 4; jp++) {
            float2 v = unpack2(acc2[i][jp]);
            int col = bcol + tx * 8 + jp * 2;
            float r0 = v.x + bias[col];
            float r1 = v.y + bias[col + 1];
            if (EPI == 1) {
                r0 = fmaxf(r0, 0.f) + log1pf(expf(-fabsf(r0)));
                r1 = fmaxf(r1, 0.f) + log1pf(expf(-fabsf(r1)));
            } else if (EPI == 2) {
                r0 = sigmoidf_(r0);
                r1 = sigmoidf_(r1);
            }
            C[row * N + col]     = r0;
            C[row * N + col + 1] = r1;
        }
    }
}

// ---------------- rotary: XR = rotate(P[:, :1024]) ----------------
__global__ void rotary_kernel(const float* __restrict__ sinp, const float* __restrict__ cosp) {
    int r = blockIdx.x;
    int t = r & (T_ - 1);
    const float* pr = g_P + (size_t)r * 2048;
    float* xr = g_XR + (size_t)r * 1024;
    for (int i = threadIdx.x; i < 512; i += 256) {
        float c = cosp[t * 512 + i], s = sinp[t * 512 + i];
        float a0 = pr[2 * i], a1 = pr[2 * i + 1];
        xr[2 * i]     = a0 * c - a1 * s;
        xr[2 * i + 1] = a0 * s + a1 * c;
    }
}

// ---------------- dwconv + gate + RMS -> glcm_out ----------------
__global__ void glcm_kernel(const float* __restrict__ Wdw, const float* __restrict__ bdw,
                            const float* __restrict__ gg) {
    int r = blockIdx.x;
    int b = r >> 9, t = r & 511;
    float vals[4];
    float ss = 0.f;
#pragma unroll
    for (int j = 0; j < 4; j++) {
        int d = threadIdx.x + j * 256;
        float conv = bdw[d];
#pragma unroll
        for (int k = 0; k < 7; k++) {
            int tt = t + k - 3;
            if (tt >= 0 && tt < T_)
                conv += g_XR[(size_t)(b * T_ + tt) * 1024 + d] * Wdw[k * 1024 + d];
        }
        float xb = g_P[(size_t)r * 2048 + 1024 + d];
        float v = conv * sigmoidf_(conv) * sigmoidf_(xb);
        vals[j] = v;
        ss += v * v;
    }
    ss = block_sum256(ss);
    float inv = 1.f / sqrtf(ss * (1.f / 1024.f) + EPS_);
#pragma unroll
    for (int j = 0; j < 4; j++) {
        int d = threadIdx.x + j * 256;
        g_glcm[(size_t)r * 1024 + d] = gg[d] * vals[j] * inv;
    }
}

// ---------------- sequential S6 scan ----------------
// one 16-lane half-warp per (b, s); n = lane&15. 1024 warps total.
__global__ void scan_kernel(const float* __restrict__ Alog) {
    int gw = (blockIdx.x * blockDim.x + threadIdx.x) >> 5;
    int lane = threadIdx.x & 31;
    int b = gw >> 9;             // 512 warps per batch
    int spair = gw & 511;
    int half = lane >> 4, n = lane & 15;
    int s = spair * 2 + half;
    float A = -expf(Alog[s * 16 + n]);
    float h = 0.f;
    const int base_r = b * T_;
    for (int t = 0; t < T_; t++) {
        int r = base_r + t;
        float d  = g_delta[(size_t)r * 1024 + s];
        float u  = g_XI[(size_t)r * 2048 + s];
        float Bv = g_Bmat[(size_t)r * 16384 + s * 16 + n];
        float Cv = g_Cmat[(size_t)r * 16384 + s * 16 + n];
        h = expf(d * A) * h + (d * u) * Bv;
        float p = h * Cv;
        p += __shfl_xor_sync(0xffffffffu, p, 1);
        p += __shfl_xor_sync(0xffffffffu, p, 2);
        p += __shfl_xor_sync(0xffffffffu, p, 4);
        p += __shfl_xor_sync(0xffffffffu, p, 8);
        if (n == 0) g_y[(size_t)r * 1024 + s] = p;
    }
}

// ---------------- RMS (yo -> s6_out) ----------------
__global__ void rms_kernel(const float* __restrict__ gg) {
    int r = blockIdx.x;
    const float* xin = g_yo + (size_t)r * 1024;
    float vals[4];
    float ss = 0.f;
#pragma unroll
    for (int j = 0; j < 4; j++) {
        int d = threadIdx.x + j * 256;
        float v = xin[d];
        vals[j] = v;
        ss += v * v;
    }
    ss = block_sum256(ss);
    float inv = 1.f / sqrtf(ss * (1.f / 1024.f) + EPS_);
#pragma unroll
    for (int j = 0; j < 4; j++) {
        int d = threadIdx.x + j * 256;
        g_s6[(size_t)r * 1024 + d] = gg[d] * vals[j] * inv;
    }
}

// ---------------- combine: h = x + rms(g1*s6 + g2*glcm, gf_g) ----------------
__global__ void combine_kernel(const float* __restrict__ x, const float* __restrict__ gfg) {
    int r = blockIdx.x;
    float vals[4];
    float ss = 0.f;
#pragma unroll
    for (int j = 0; j < 4; j++) {
        int d = threadIdx.x + j * 256;
        size_t idx = (size_t)r * 1024 + d;
        float v = g_g1[idx] * g_s6[idx] + g_g2[idx] * g_glcm[idx];
        vals[j] = v;
        ss += v * v;
    }
    ss = block_sum256(ss);
    float inv = 1.f / sqrtf(ss * (1.f / 1024.f) + EPS_);
#pragma unroll
    for (int j = 0; j < 4; j++) {
        int d = threadIdx.x + j * 256;
        size_t idx = (size_t)r * 1024 + d;
        g_h[idx] = x[idx] + gfg[d] * vals[j] * inv;
    }
}

// ---------------- MoE routing ----------------
__global__ void zero_cnt_kernel() {
    if (threadIdx.x < E_) g_cnt[threadIdx.x] = 0;
}

__global__ void route_kernel(const float* __restrict__ Wg) {
    int warp = threadIdx.x >> 5, lane = threadIdx.x & 31;
    int token = blockIdx.x * 8 + warp;
    float acc[16];
#pragma unroll
    for (int e = 0; e < 16; e++) acc[e] = 0.f;
    const float* hrow = g_h + (size_t)token * 1024;
    for (int d = lane; d < 1024; d += 32) {
        float xv = hrow[d];
#pragma unroll
        for (int e = 0; e < 16; e++) acc[e] += xv * Wg[d * 16 + e];
    }
#pragma unroll
    for (int e = 0; e < 16; e++) {
#pragma unroll
        for (int o = 16; o; o >>= 1) acc[e] += __shfl_xor_sync(0xffffffffu, acc[e], o);
    }
    if (lane == 0) {
        float v0 = -1e30f; int i0 = 0;
#pragma unroll
        for (int e = 0; e < 16; e++) if (acc[e] > v0) { v0 = acc[e]; i0 = e; }
        float v1 = -1e30f; int i1 = 0;
#pragma unroll
        for (int e = 0; e < 16; e++) if (e != i0 && acc[e] > v1) { v1 = acc[e]; i1 = e; }
        float w0 = 1.f / (1.f + expf(v1 - v0));
        g_w[token * 2]     = w0;
        g_w[token * 2 + 1] = 1.f - w0;
        int p0 = atomicAdd(&g_cnt[i0], 1);
        g_list[i0 * 1024 + p0] = token * 2;
        int p1 = atomicAdd(&g_cnt[i1], 1);
        g_list[i1 * 1024 + p1] = token * 2 + 1;
    }
}

// ---------------- MoE grouped gather-GEMM ----------------
// PHASE 1: e1[a] = silu(h[token(a)] @ W1[e] + b1[e]),  K=1024, N=4096
// PHASE 2: e2[a] = (e1[a] @ W2[e] + b2[e]) * w[a],     K=4096, N=1024
template <int PHASE>
__global__ __launch_bounds__(256)
void moe_gemm_kernel(const float* __restrict__ Wall, const float* __restrict__ ball) {
    constexpr int K = (PHASE == 1) ? 1024 : 4096;
    constexpr int N = (PHASE == 1) ? 4096 : 1024;
    int e = blockIdx.z;
    int mc = g_cnt[e];
    int m0 = blockIdx.y * 128;
    if (m0 >= mc) return;
    const float* Asrc = (PHASE == 1) ? g_h : g_e1;
    float* Cd = (PHASE == 1) ? g_e1 : g_e2;
    const float* W = Wall + (size_t)e * K * N;
    const float* bias = ball + (size_t)e * N;

    __shared__ int rows[128];
    __shared__ float As[16][128];
    __shared__ float Bs[16][132];

    int tid = threadIdx.x;
    if (tid < 128) {
        int m = m0 + tid;
        rows[tid] = (m < mc) ? g_list[e * 1024 + m] : -1;
    }
    __syncthreads();

    int tx = tid & 15, ty = tid >> 4;
    unsigned long long acc2[8][4] = {};
    int bcol = blockIdx.x * 128;

    for (int k0 = 0; k0 < K; k0 += 16) {
#pragma unroll
        for (int i = 0; i < 2; i++) {
            int v = tid * 2 + i;
            int r = v >> 2, c4 = v & 3;
            int a = rows[r];
            float4 tv = make_float4(0.f, 0.f, 0.f, 0.f);
            if (a >= 0) {
                size_t srow = (PHASE == 1) ? (size_t)(a >> 1) : (size_t)a;
                tv = *(const float4*)(Asrc + srow * K + k0 + c4 * 4);
            }
            As[c4 * 4 + 0][r] = tv.x;
            As[c4 * 4 + 1][r] = tv.y;
            As[c4 * 4 + 2][r] = tv.z;
            As[c4 * 4 + 3][r] = tv.w;
        }
#pragma unroll
        for (int i = 0; i < 2; i++) {
            int v = tid * 2 + i;
            int r = v >> 5, c4 = v & 31;
            *(float4*)(&Bs[r][c4 * 4]) = *(const float4*)(W + (size_t)(k0 + r) * N + bcol + c4 * 4);
        }
        __syncthreads();
#pragma unroll
        for (int kk = 0; kk < 16; kk++) {
            float4 alo = *(const float4*)&As[kk][ty * 8];
            float4 ahi = *(const float4*)&As[kk][ty * 8 + 4];
            const unsigned long long* bp = (const unsigned long long*)&Bs[kk][tx * 8];
            unsigned long long b2[4];
            b2[0] = bp[0]; b2[1] = bp[1]; b2[2] = bp[2]; b2[3] = bp[3];
            float av[8] = {alo.x, alo.y, alo.z, alo.w, ahi.x, ahi.y, ahi.z, ahi.w};
#pragma unroll
            for (int i = 0; i < 8; i++) {
                unsigned long long a2 = pack2(av[i], av[i]);
#pragma unroll
                for (int jp = 0; jp < 4; jp++) fma2(acc2[i][jp], a2, b2[jp]);
            }
        }
        __syncthreads();
    }

#pragma unroll
    for (int i = 0; i < 8; i++) {
        int a = rows[ty * 8 + i];
        if (a < 0) continue;
        float wscale = (PHASE == 2) ? g_w[a] : 1.f;
#pragma unroll
        for (int jp = 0; jp < 4; jp++) {
            float2 v = unpack2(acc2[i][jp]);
            int col = bcol + tx * 8 + jp * 2;
            float r0 = v.x + bias[col];
            float r1 = v.y + bias[col + 1];
            if (PHASE == 1) {
                r0 = r0 * sigmoidf_(r0);
                r1 = r1 * sigmoidf_(r1);
            } else {
                r0 *= wscale;
                r1 *= wscale;
            }
            Cd[(size_t)a * N + col]     = r0;
            Cd[(size_t)a * N + col + 1] = r1;
        }
    }
}

// ---------------- final: out = h + e2[token,0] + e2[token,1] ----------------
__global__ void final_kernel(float* __restrict__ out) {
    int idx = blockIdx.x * 256 + threadIdx.x;
    int r = idx >> 10, d = idx & 1023;
    out[idx] = g_h[idx] + g_e2[(size_t)r * 2048 + d] + g_e2[(size_t)r * 2048 + 1024 + d];
}

// ---------------- launch ----------------
extern "C" void kernel_launch(void* const* d_in, const int* /*in_sizes*/, int /*n_in*/,
                              void* d_out, int /*out_size*/) {
    const float* x    = (const float*)d_in[0];
    const float* sinp = (const float*)d_in[1];
    const float* cosp = (const float*)d_in[2];
    const float* Wp   = (const float*)d_in[3];
    const float* bp   = (const float*)d_in[4];
    const float* Wdw  = (const float*)d_in[5];
    const float* bdw  = (const float*)d_in[6];
    const float* glg  = (const float*)d_in[7];
    const float* Win  = (const float*)d_in[8];
    const float* bin  = (const float*)d_in[9];
    const float* Wd   = (const float*)d_in[10];
    const float* bd   = (const float*)d_in[11];
    const float* WB   = (const float*)d_in[12];
    const float* bB   = (const float*)d_in[13];
    const float* WC   = (const float*)d_in[14];
    const float* bC   = (const float*)d_in[15];
    const float* Alog = (const float*)d_in[16];
    const float* Wout = (const float*)d_in[17];
    const float* bout = (const float*)d_in[18];
    const float* s6g  = (const float*)d_in[19];
    const float* gfW1 = (const float*)d_in[20];
    const float* gfb1 = (const float*)d_in[21];
    const float* gfW2 = (const float*)d_in[22];
    const float* gfb2 = (const float*)d_in[23];
    const float* gfg  = (const float*)d_in[24];
    const float* Wg   = (const float*)d_in[25];
    const float* mW1  = (const float*)d_in[26];
    const float* mb1  = (const float*)d_in[27];
    const float* mW2  = (const float*)d_in[28];
    const float* mb2  = (const float*)d_in[29];
    float* out = (float*)d_out;

    // pointers to device scratch for the generic GEMM
    float *pP, *pXI, *pDelta, *pB, *pC, *pY, *pYO, *pG1, *pG2;
    cudaGetSymbolAddress((void**)&pP,     g_P);
    cudaGetSymbolAddress((void**)&pXI,    g_XI);
    cudaGetSymbolAddress((void**)&pDelta, g_delta);
    cudaGetSymbolAddress((void**)&pB,     g_Bmat);
    cudaGetSymbolAddress((void**)&pC,     g_Cmat);
    cudaGetSymbolAddress((void**)&pY,     g_y);
    cudaGetSymbolAddress((void**)&pYO,    g_yo);
    cudaGetSymbolAddress((void**)&pG1,    g_g1);
    cudaGetSymbolAddress((void**)&pG2,    g_g2);

    // 1) P = x @ Wp + bp  [1024 x 2048]
    sgemm_kernel<0><<<dim3(16, 8), 256>>>(x, Wp, bp, pP, BT, 2048, 1024);
    // 2) XI = x @ Win + bin  [1024 x 2048]
    sgemm_kernel<0><<<dim3(16, 8), 256>>>(x, Win, bin, pXI, BT, 2048, 1024);
    // 3) rotary on xa -> XR
    rotary_kernel<<<BT, 256>>>(sinp, cosp);
    // 4) dwconv + gate + rms -> glcm_out
    glcm_kernel<<<BT, 256>>>(Wdw, bdw, glg);
    // 5) delta = softplus(XI @ Wd + bd)  [1024 x 1024]
    sgemm_kernel<1><<<dim3(8, 8), 256>>>(pXI, Wd, bd, pDelta, BT, 1024, 2048);
    // 6) Bm = XI @ WB + bB  [1024 x 16384]
    sgemm_kernel<0><<<dim3(128, 8), 256>>>(pXI, WB, bB, pB, BT, 16384, 2048);
    // 7) Cm = XI @ WC + bC  [1024 x 16384]
    sgemm_kernel<0><<<dim3(128, 8), 256>>>(pXI, WC, bC, pC, BT, 16384, 2048);
    // 8) sequential scan -> y
    scan_kernel<<<128, 256>>>(Alog);
    // 9) yo = y @ Wout + bout ; s6 = rms(yo)
    sgemm_kernel<0><<<dim3(8, 8), 256>>>(pY, Wout, bout, pYO, BT, 1024, 1024);
    rms_kernel<<<BT, 256>>>(s6g);
    // 10) g1, g2 gates
    sgemm_kernel<2><<<dim3(8, 8), 256>>>(x, gfW1, gfb1, pG1, BT, 1024, 1024);
    sgemm_kernel<2><<<dim3(8, 8), 256>>>(x, gfW2, gfb2, pG2, BT, 1024, 1024);
    // 11) h = x + rms(g1*s6 + g2*glcm)
    combine_kernel<<<BT, 256>>>(x, gfg);
    // 12) MoE routing
    zero_cnt_kernel<<<1, 32>>>();
    route_kernel<<<128, 256>>>(Wg);
    // 13) expert FFN phase 1 (silu)
    moe_gemm_kernel<1><<<dim3(32, 8, 16), 256>>>(mW1, mb1);
    // 14) expert FFN phase 2 (weighted)
    moe_gemm_kernel<2><<<dim3(8, 8, 16), 256>>>(mW2, mb2);
    // 15) final output
    final_kernel<<<4096, 256>>>(out);
}

// round 5
// speedup vs baseline: 2.9527x; 2.9527x over previous
#include <cuda_runtime.h>
#include <cuda_bf16.h>
#include <math.h>
#include <stdint.h>

// ---------------- constants ----------------
constexpr int D_  = 1024;
constexpr int S_  = 1024;
constexpr int N_  = 16;
constexpr int E_  = 16;
constexpr int T_  = 512;
constexpr int BT  = 1024;   // B*T
constexpr float EPS_ = 1e-8f;

// ---------------- scratch (static device globals; no allocations) ----------------
__device__ float g_P    [BT * 2048];
__device__ float g_XI   [BT * 2048];
__device__ float g_XR   [BT * D_];
__device__ float g_glcm [BT * D_];
__device__ float g_delta[BT * S_];
__device__ float g_Bmat [BT * S_ * N_];
__device__ float g_Cmat [BT * S_ * N_];
__device__ float g_y    [BT * S_];
__device__ float g_yo   [BT * D_];
__device__ float g_s6   [BT * D_];
__device__ float g_g1   [BT * D_];
__device__ float g_g2   [BT * D_];
__device__ float g_h    [BT * D_];
__device__ float g_e1   [2 * BT * 4096];
__device__ float g_e2   [2 * BT * D_];
__device__ int   g_cnt  [E_];
__device__ int   g_list [E_ * 2048];
__device__ float g_w    [2 * BT];

// ---------------- helpers ----------------
__device__ __forceinline__ float sigmoidf_(float x) { return 1.f / (1.f + expf(-x)); }

__device__ __forceinline__ float block_sum256(float v) {
    __shared__ float sh[8];
    int lane = threadIdx.x & 31, w = threadIdx.x >> 5;
#pragma unroll
    for (int o = 16; o; o >>= 1) v += __shfl_xor_sync(0xffffffffu, v, o);
    if (lane == 0) sh[w] = v;
    __syncthreads();
    float s = 0.f;
#pragma unroll
    for (int i = 0; i < 8; i++) s += sh[i];
    return s;
}

__device__ __forceinline__ uint32_t smem_u32(const void* p) {
    return (uint32_t)__cvta_generic_to_shared(p);
}

__device__ __forceinline__ void ldsm_x4(uint32_t& r0, uint32_t& r1, uint32_t& r2, uint32_t& r3, uint32_t addr) {
    asm volatile("ldmatrix.sync.aligned.m8n8.x4.shared.b16 {%0,%1,%2,%3}, [%4];"
        : "=r"(r0), "=r"(r1), "=r"(r2), "=r"(r3) : "r"(addr));
}
__device__ __forceinline__ void ldsm_x4_t(uint32_t& r0, uint32_t& r1, uint32_t& r2, uint32_t& r3, uint32_t addr) {
    asm volatile("ldmatrix.sync.aligned.m8n8.x4.trans.shared.b16 {%0,%1,%2,%3}, [%4];"
        : "=r"(r0), "=r"(r1), "=r"(r2), "=r"(r3) : "r"(addr));
}
__device__ __forceinline__ void mma_bf16(float* c, const uint32_t* a, const uint32_t* b) {
    asm volatile("mma.sync.aligned.m16n8k16.row.col.f32.bf16.bf16.f32 "
        "{%0,%1,%2,%3}, {%4,%5,%6,%7}, {%8,%9}, {%0,%1,%2,%3};"
        : "+f"(c[0]), "+f"(c[1]), "+f"(c[2]), "+f"(c[3])
        : "r"(a[0]), "r"(a[1]), "r"(a[2]), "r"(a[3]), "r"(b[0]), "r"(b[1]));
}

// split 16 f32 -> 8 packed-bf16x2 hi words + 8 lo words
__device__ __forceinline__ void cvt_split16(const float* v, uint32_t* hi, uint32_t* lo) {
#pragma unroll
    for (int i = 0; i < 8; i++) {
        float x0 = v[2 * i], x1 = v[2 * i + 1];
        __nv_bfloat16 h0 = __float2bfloat16(x0), h1 = __float2bfloat16(x1);
        float r0 = x0 - __bfloat162float(h0), r1 = x1 - __bfloat162float(h1);
        __nv_bfloat16 l0 = __float2bfloat16(r0), l1 = __float2bfloat16(r1);
        hi[i] = ((uint32_t)__bfloat16_as_ushort(h1) << 16) | __bfloat16_as_ushort(h0);
        lo[i] = ((uint32_t)__bfloat16_as_ushort(l1) << 16) | __bfloat16_as_ushort(l0);
    }
}

// ============================================================================
// Tensor-core GEMM: C[M,N] = A[M,K] @ W[K,N] + bias  (bf16-split, f32 accum)
// CTA tile 128x128, KTILE=32, 256 threads = 8 warps (2m x 4n), warp 64x32.
// grid: (M/128, N/128) -- M on x so a wave shares W column tiles.
// EPI: 0 none, 1 softplus, 2 sigmoid
// ============================================================================
constexpr int A_STR = 40;   // halfs per A smem row (32 + 8 pad)
constexpr int B_STR = 136;  // halfs per B smem row (128 + 8 pad)

template <int EPI>
__global__ __launch_bounds__(256)
void tgemm_kernel(const float* __restrict__ A, const float* __restrict__ W,
                  const float* __restrict__ bias, float* __restrict__ C,
                  int M, int N, int K) {
    __shared__ __nv_bfloat16 sAh[128][A_STR];
    __shared__ __nv_bfloat16 sAl[128][A_STR];
    __shared__ __nv_bfloat16 sBh[32][B_STR];
    __shared__ __nv_bfloat16 sBl[32][B_STR];

    const int tid = threadIdx.x;
    const int warp = tid >> 5, lane = tid & 31;
    const int wm = warp & 1, wn = warp >> 1;
    const int mBase = blockIdx.x * 128;
    const int nBase = blockIdx.y * 128;
    const int wmBase = wm * 64, wnBase = wn * 32;

    // loader indices
    const int arow = tid >> 1, acb = (tid & 1) * 16;
    const int brow = tid >> 3, bcb = (tid & 7) * 16;

    // ldmatrix base addresses
    const int lrow = lane & 15;
    const int lcol = (lane >> 4) << 3;
    const uint32_t aBaseH = smem_u32(&sAh[wmBase + lrow][lcol]);
    const uint32_t aBaseL = smem_u32(&sAl[wmBase + lrow][lcol]);
    const uint32_t bBaseH = smem_u32(&sBh[lrow][wnBase + lcol]);
    const uint32_t bBaseL = smem_u32(&sBl[lrow][wnBase + lcol]);

    float acc[4][4][4] = {};

    for (int k0 = 0; k0 < K; k0 += 32) {
        // stage A (128x32 f32 -> hi/lo bf16)
        {
            const float* ap = A + (size_t)(mBase + arow) * K + k0 + acb;
            float av[16];
            *(float4*)&av[0]  = *(const float4*)(ap);
            *(float4*)&av[4]  = *(const float4*)(ap + 4);
            *(float4*)&av[8]  = *(const float4*)(ap + 8);
            *(float4*)&av[12] = *(const float4*)(ap + 12);
            uint32_t hi[8], lo[8];
            cvt_split16(av, hi, lo);
            *(uint4*)&sAh[arow][acb]     = *(uint4*)&hi[0];
            *(uint4*)&sAh[arow][acb + 8] = *(uint4*)&hi[4];
            *(uint4*)&sAl[arow][acb]     = *(uint4*)&lo[0];
            *(uint4*)&sAl[arow][acb + 8] = *(uint4*)&lo[4];
        }
        // stage B (32x128 f32 -> hi/lo bf16)
        {
            const float* bp = W + (size_t)(k0 + brow) * N + nBase + bcb;
            float bv[16];
            *(float4*)&bv[0]  = *(const float4*)(bp);
            *(float4*)&bv[4]  = *(const float4*)(bp + 4);
            *(float4*)&bv[8]  = *(const float4*)(bp + 8);
            *(float4*)&bv[12] = *(const float4*)(bp + 12);
            uint32_t hi[8], lo[8];
            cvt_split16(bv, hi, lo);
            *(uint4*)&sBh[brow][bcb]     = *(uint4*)&hi[0];
            *(uint4*)&sBh[brow][bcb + 8] = *(uint4*)&hi[4];
            *(uint4*)&sBl[brow][bcb]     = *(uint4*)&lo[0];
            *(uint4*)&sBl[brow][bcb + 8] = *(uint4*)&lo[4];
        }
        __syncthreads();

#pragma unroll
        for (int chunk = 0; chunk < 2; chunk++) {
            uint32_t Ah[4][4], Al[4][4], Bh[4][2], Bl[4][2];
#pragma unroll
            for (int mi = 0; mi < 4; mi++) {
                ldsm_x4(Ah[mi][0], Ah[mi][1], Ah[mi][2], Ah[mi][3],
                        aBaseH + mi * (16 * A_STR * 2) + chunk * 32);
                ldsm_x4(Al[mi][0], Al[mi][1], Al[mi][2], Al[mi][3],
                        aBaseL + mi * (16 * A_STR * 2) + chunk * 32);
            }
#pragma unroll
            for (int g = 0; g < 2; g++) {
                uint32_t r0, r1, r2, r3;
                ldsm_x4_t(r0, r1, r2, r3, bBaseH + chunk * (16 * B_STR * 2) + g * 32);
                Bh[2 * g][0] = r0; Bh[2 * g][1] = r1; Bh[2 * g + 1][0] = r2; Bh[2 * g + 1][1] = r3;
                ldsm_x4_t(r0, r1, r2, r3, bBaseL + chunk * (16 * B_STR * 2) + g * 32);
                Bl[2 * g][0] = r0; Bl[2 * g][1] = r1; Bl[2 * g + 1][0] = r2; Bl[2 * g + 1][1] = r3;
            }
#pragma unroll
            for (int mi = 0; mi < 4; mi++)
#pragma unroll
                for (int ni = 0; ni < 4; ni++) {
                    mma_bf16(acc[mi][ni], Ah[mi], Bh[ni]);
                    mma_bf16(acc[mi][ni], Ah[mi], Bl[ni]);
                    mma_bf16(acc[mi][ni], Al[mi], Bh[ni]);
                }
        }
        __syncthreads();
    }

    // epilogue
    const int lr = lane >> 2, lc = (lane & 3) * 2;
#pragma unroll
    for (int mi = 0; mi < 4; mi++) {
        size_t row = (size_t)(mBase + wmBase + mi * 16 + lr);
#pragma unroll
        for (int ni = 0; ni < 4; ni++) {
            int col = nBase + wnBase + ni * 8 + lc;
            float b0 = bias[col], b1 = bias[col + 1];
            float v[4] = {acc[mi][ni][0] + b0, acc[mi][ni][1] + b1,
                          acc[mi][ni][2] + b0, acc[mi][ni][3] + b1};
#pragma unroll
            for (int q = 0; q < 4; q++) {
                if (EPI == 1) v[q] = fmaxf(v[q], 0.f) + log1pf(expf(-fabsf(v[q])));
                else if (EPI == 2) v[q] = sigmoidf_(v[q]);
            }
            *(float2*)(C + row * N + col)       = make_float2(v[0], v[1]);
            *(float2*)(C + (row + 8) * N + col) = make_float2(v[2], v[3]);
        }
    }
}

// ============================================================================
// MoE gather-GEMM (same core, indirect rows)
// PHASE 1: e1[a] = silu(h[a>>1] @ W1[e] + b1[e]),  K=1024, N=4096
// PHASE 2: e2[a] = (e1[a] @ W2[e] + b2[e]) * w[a], K=4096, N=1024
// grid: (16 rowblocks, N/128, E)
// ============================================================================
template <int PHASE>
__global__ __launch_bounds__(256)
void moe_tgemm_kernel(const float* __restrict__ Wall, const float* __restrict__ ball) {
    constexpr int K = (PHASE == 1) ? 1024 : 4096;
    constexpr int N = (PHASE == 1) ? 4096 : 1024;
    const int e = blockIdx.z;
    const int mc = g_cnt[e];
    const int m0 = blockIdx.x * 128;
    if (m0 >= mc) return;
    const float* Asrc = (PHASE == 1) ? g_h : g_e1;
    float* Cd = (PHASE == 1) ? g_e1 : g_e2;
    const float* W = Wall + (size_t)e * K * N;
    const float* bias = ball + (size_t)e * N;

    __shared__ int rows[128];
    __shared__ __nv_bfloat16 sAh[128][A_STR];
    __shared__ __nv_bfloat16 sAl[128][A_STR];
    __shared__ __nv_bfloat16 sBh[32][B_STR];
    __shared__ __nv_bfloat16 sBl[32][B_STR];

    const int tid = threadIdx.x;
    const int warp = tid >> 5, lane = tid & 31;
    const int wm = warp & 1, wn = warp >> 1;
    const int nBase = blockIdx.y * 128;
    const int wmBase = wm * 64, wnBase = wn * 32;

    if (tid < 128) {
        int m = m0 + tid;
        rows[tid] = (m < mc) ? g_list[e * 2048 + m] : -1;
    }
    __syncthreads();

    const int arow = tid >> 1, acb = (tid & 1) * 16;
    const int brow = tid >> 3, bcb = (tid & 7) * 16;
    const int arid = rows[arow];
    const size_t srow = (PHASE == 1) ? (size_t)(arid >> 1) : (size_t)arid;

    const int lrow = lane & 15;
    const int lcol = (lane >> 4) << 3;
    const uint32_t aBaseH = smem_u32(&sAh[wmBase + lrow][lcol]);
    const uint32_t aBaseL = smem_u32(&sAl[wmBase + lrow][lcol]);
    const uint32_t bBaseH = smem_u32(&sBh[lrow][wnBase + lcol]);
    const uint32_t bBaseL = smem_u32(&sBl[lrow][wnBase + lcol]);

    float acc[4][4][4] = {};

    for (int k0 = 0; k0 < K; k0 += 32) {
        {
            float av[16];
            if (arid >= 0) {
                const float* ap = Asrc + srow * K + k0 + acb;
                *(float4*)&av[0]  = *(const float4*)(ap);
                *(float4*)&av[4]  = *(const float4*)(ap + 4);
                *(float4*)&av[8]  = *(const float4*)(ap + 8);
                *(float4*)&av[12] = *(const float4*)(ap + 12);
            } else {
#pragma unroll
                for (int i = 0; i < 16; i++) av[i] = 0.f;
            }
            uint32_t hi[8], lo[8];
            cvt_split16(av, hi, lo);
            *(uint4*)&sAh[arow][acb]     = *(uint4*)&hi[0];
            *(uint4*)&sAh[arow][acb + 8] = *(uint4*)&hi[4];
            *(uint4*)&sAl[arow][acb]     = *(uint4*)&lo[0];
            *(uint4*)&sAl[arow][acb + 8] = *(uint4*)&lo[4];
        }
        {
            const float* bp = W + (size_t)(k0 + brow) * N + nBase + bcb;
            float bv[16];
            *(float4*)&bv[0]  = *(const float4*)(bp);
            *(float4*)&bv[4]  = *(const float4*)(bp + 4);
            *(float4*)&bv[8]  = *(const float4*)(bp + 8);
            *(float4*)&bv[12] = *(const float4*)(bp + 12);
            uint32_t hi[8], lo[8];
            cvt_split16(bv, hi, lo);
            *(uint4*)&sBh[brow][bcb]     = *(uint4*)&hi[0];
            *(uint4*)&sBh[brow][bcb + 8] = *(uint4*)&hi[4];
            *(uint4*)&sBl[brow][bcb]     = *(uint4*)&lo[0];
            *(uint4*)&sBl[brow][bcb + 8] = *(uint4*)&lo[4];
        }
        __syncthreads();

#pragma unroll
        for (int chunk = 0; chunk < 2; chunk++) {
            uint32_t Ah[4][4], Al[4][4], Bh[4][2], Bl[4][2];
#pragma unroll
            for (int mi = 0; mi < 4; mi++) {
                ldsm_x4(Ah[mi][0], Ah[mi][1], Ah[mi][2], Ah[mi][3],
                        aBaseH + mi * (16 * A_STR * 2) + chunk * 32);
                ldsm_x4(Al[mi][0], Al[mi][1], Al[mi][2], Al[mi][3],
                        aBaseL + mi * (16 * A_STR * 2) + chunk * 32);
            }
#pragma unroll
            for (int g = 0; g < 2; g++) {
                uint32_t r0, r1, r2, r3;
                ldsm_x4_t(r0, r1, r2, r3, bBaseH + chunk * (16 * B_STR * 2) + g * 32);
                Bh[2 * g][0] = r0; Bh[2 * g][1] = r1; Bh[2 * g + 1][0] = r2; Bh[2 * g + 1][1] = r3;
                ldsm_x4_t(r0, r1, r2, r3, bBaseL + chunk * (16 * B_STR * 2) + g * 32);
                Bl[2 * g][0] = r0; Bl[2 * g][1] = r1; Bl[2 * g + 1][0] = r2; Bl[2 * g + 1][1] = r3;
            }
#pragma unroll
            for (int mi = 0; mi < 4; mi++)
#pragma unroll
                for (int ni = 0; ni < 4; ni++) {
                    mma_bf16(acc[mi][ni], Ah[mi], Bh[ni]);
                    mma_bf16(acc[mi][ni], Ah[mi], Bl[ni]);
                    mma_bf16(acc[mi][ni], Al[mi], Bh[ni]);
                }
        }
        __syncthreads();
    }

    const int lr = lane >> 2, lc = (lane & 3) * 2;
#pragma unroll
    for (int mi = 0; mi < 4; mi++) {
        int a0 = rows[wmBase + mi * 16 + lr];
        int a1 = rows[wmBase + mi * 16 + lr + 8];
        float w0 = (PHASE == 2 && a0 >= 0) ? g_w[a0] : 1.f;
        float w1 = (PHASE == 2 && a1 >= 0) ? g_w[a1] : 1.f;
#pragma unroll
        for (int ni = 0; ni < 4; ni++) {
            int col = nBase + wnBase + ni * 8 + lc;
            float b0 = bias[col], b1 = bias[col + 1];
            float v00 = acc[mi][ni][0] + b0, v01 = acc[mi][ni][1] + b1;
            float v10 = acc[mi][ni][2] + b0, v11 = acc[mi][ni][3] + b1;
            if (PHASE == 1) {
                v00 *= sigmoidf_(v00); v01 *= sigmoidf_(v01);
                v10 *= sigmoidf_(v10); v11 *= sigmoidf_(v11);
            } else {
                v00 *= w0; v01 *= w0; v10 *= w1; v11 *= w1;
            }
            if (a0 >= 0) *(float2*)(Cd + (size_t)a0 * N + col) = make_float2(v00, v01);
            if (a1 >= 0) *(float2*)(Cd + (size_t)a1 * N + col) = make_float2(v10, v11);
        }
    }
}

// ---------------- rotary: XR = rotate(P[:, :1024]) ----------------
__global__ void rotary_kernel(const float* __restrict__ sinp, const float* __restrict__ cosp) {
    int r = blockIdx.x;
    int t = r & (T_ - 1);
    const float* pr = g_P + (size_t)r * 2048;
    float* xr = g_XR + (size_t)r * 1024;
    for (int i = threadIdx.x; i < 512; i += 256) {
        float c = cosp[t * 512 + i], s = sinp[t * 512 + i];
        float a0 = pr[2 * i], a1 = pr[2 * i + 1];
        xr[2 * i]     = a0 * c - a1 * s;
        xr[2 * i + 1] = a0 * s + a1 * c;
    }
}

// ---------------- dwconv + gate + RMS -> glcm_out ----------------
__global__ void glcm_kernel(const float* __restrict__ Wdw, const float* __restrict__ bdw,
                            const float* __restrict__ gg) {
    int r = blockIdx.x;
    int b = r >> 9, t = r & 511;
    float vals[4];
    float ss = 0.f;
#pragma unroll
    for (int j = 0; j < 4; j++) {
        int d = threadIdx.x + j * 256;
        float conv = bdw[d];
#pragma unroll
        for (int k = 0; k < 7; k++) {
            int tt = t + k - 3;
            if (tt >= 0 && tt < T_)
                conv += g_XR[(size_t)(b * T_ + tt) * 1024 + d] * Wdw[k * 1024 + d];
        }
        float xb = g_P[(size_t)r * 2048 + 1024 + d];
        float v = conv * sigmoidf_(conv) * sigmoidf_(xb);
        vals[j] = v;
        ss += v * v;
    }
    ss = block_sum256(ss);
    float inv = 1.f / sqrtf(ss * (1.f / 1024.f) + EPS_);
#pragma unroll
    for (int j = 0; j < 4; j++) {
        int d = threadIdx.x + j * 256;
        g_glcm[(size_t)r * 1024 + d] = gg[d] * vals[j] * inv;
    }
}

// ---------------- sequential S6 scan ----------------
__global__ void scan_kernel(const float* __restrict__ Alog) {
    int gw = (blockIdx.x * blockDim.x + threadIdx.x) >> 5;
    int lane = threadIdx.x & 31;
    int b = gw >> 9;
    int spair = gw & 511;
    int half = lane >> 4, n = lane & 15;
    int s = spair * 2 + half;
    float A = -expf(Alog[s * 16 + n]);
    float h = 0.f;
    const int base_r = b * T_;
    for (int t = 0; t < T_; t++) {
        int r = base_r + t;
        float d  = g_delta[(size_t)r * 1024 + s];
        float u  = g_XI[(size_t)r * 2048 + s];
        float Bv = g_Bmat[(size_t)r * 16384 + s * 16 + n];
        float Cv = g_Cmat[(size_t)r * 16384 + s * 16 + n];
        h = expf(d * A) * h + (d * u) * Bv;
        float p = h * Cv;
        p += __shfl_xor_sync(0xffffffffu, p, 1);
        p += __shfl_xor_sync(0xffffffffu, p, 2);
        p += __shfl_xor_sync(0xffffffffu, p, 4);
        p += __shfl_xor_sync(0xffffffffu, p, 8);
        if (n == 0) g_y[(size_t)r * 1024 + s] = p;
    }
}

// ---------------- RMS (yo -> s6_out) ----------------
__global__ void rms_kernel(const float* __restrict__ gg) {
    int r = blockIdx.x;
    const float* xin = g_yo + (size_t)r * 1024;
    float vals[4];
    float ss = 0.f;
#pragma unroll
    for (int j = 0; j < 4; j++) {
        int d = threadIdx.x + j * 256;
        float v = xin[d];
        vals[j] = v;
        ss += v * v;
    }
    ss = block_sum256(ss);
    float inv = 1.f / sqrtf(ss * (1.f / 1024.f) + EPS_);
#pragma unroll
    for (int j = 0; j < 4; j++) {
        int d = threadIdx.x + j * 256;
        g_s6[(size_t)r * 1024 + d] = gg[d] * vals[j] * inv;
    }
}

// ---------------- combine: h = x + rms(g1*s6 + g2*glcm, gf_g) ----------------
__global__ void combine_kernel(const float* __restrict__ x, const float* __restrict__ gfg) {
    int r = blockIdx.x;
    float vals[4];
    float ss = 0.f;
#pragma unroll
    for (int j = 0; j < 4; j++) {
        int d = threadIdx.x + j * 256;
        size_t idx = (size_t)r * 1024 + d;
        float v = g_g1[idx] * g_s6[idx] + g_g2[idx] * g_glcm[idx];
        vals[j] = v;
        ss += v * v;
    }
    ss = block_sum256(ss);
    float inv = 1.f / sqrtf(ss * (1.f / 1024.f) + EPS_);
#pragma unroll
    for (int j = 0; j < 4; j++) {
        int d = threadIdx.x + j * 256;
        size_t idx = (size_t)r * 1024 + d;
        g_h[idx] = x[idx] + gfg[d] * vals[j] * inv;
    }
}

// ---------------- MoE routing ----------------
__global__ void zero_cnt_kernel() {
    if (threadIdx.x < E_) g_cnt[threadIdx.x] = 0;
}

__global__ void route_kernel(const float* __restrict__ Wg) {
    int warp = threadIdx.x >> 5, lane = threadIdx.x & 31;
    int token = blockIdx.x * 8 + warp;
    float acc[16];
#pragma unroll
    for (int e = 0; e < 16; e++) acc[e] = 0.f;
    const float* hrow = g_h + (size_t)token * 1024;
    for (int d = lane; d < 1024; d += 32) {
        float xv = hrow[d];
#pragma unroll
        for (int e = 0; e < 16; e++) acc[e] += xv * Wg[d * 16 + e];
    }
#pragma unroll
    for (int e = 0; e < 16; e++) {
#pragma unroll
        for (int o = 16; o; o >>= 1) acc[e] += __shfl_xor_sync(0xffffffffu, acc[e], o);
    }
    if (lane == 0) {
        float v0 = -1e30f; int i0 = 0;
#pragma unroll
        for (int e = 0; e < 16; e++) if (acc[e] > v0) { v0 = acc[e]; i0 = e; }
        float v1 = -1e30f; int i1 = 0;
#pragma unroll
        for (int e = 0; e < 16; e++) if (e != i0 && acc[e] > v1) { v1 = acc[e]; i1 = e; }
        float w0 = 1.f / (1.f + expf(v1 - v0));
        g_w[token * 2]     = w0;
        g_w[token * 2 + 1] = 1.f - w0;
        int p0 = atomicAdd(&g_cnt[i0], 1);
        g_list[i0 * 2048 + p0] = token * 2;
        int p1 = atomicAdd(&g_cnt[i1], 1);
        g_list[i1 * 2048 + p1] = token * 2 + 1;
    }
}

// ---------------- final: out = h + e2[token,0] + e2[token,1] ----------------
__global__ void final_kernel(float* __restrict__ out) {
    int idx = blockIdx.x * 256 + threadIdx.x;
    int r = idx >> 10, d = idx & 1023;
    out[idx] = g_h[idx] + g_e2[(size_t)r * 2048 + d] + g_e2[(size_t)r * 2048 + 1024 + d];
}

// ---------------- launch ----------------
extern "C" void kernel_launch(void* const* d_in, const int* /*in_sizes*/, int /*n_in*/,
                              void* d_out, int /*out_size*/) {
    const float* x    = (const float*)d_in[0];
    const float* sinp = (const float*)d_in[1];
    const float* cosp = (const float*)d_in[2];
    const float* Wp   = (const float*)d_in[3];
    const float* bp   = (const float*)d_in[4];
    const float* Wdw  = (const float*)d_in[5];
    const float* bdw  = (const float*)d_in[6];
    const float* glg  = (const float*)d_in[7];
    const float* Win  = (const float*)d_in[8];
    const float* bin  = (const float*)d_in[9];
    const float* Wd   = (const float*)d_in[10];
    const float* bd   = (const float*)d_in[11];
    const float* WB   = (const float*)d_in[12];
    const float* bB   = (const float*)d_in[13];
    const float* WC   = (const float*)d_in[14];
    const float* bC   = (const float*)d_in[15];
    const float* Alog = (const float*)d_in[16];
    const float* Wout = (const float*)d_in[17];
    const float* bout = (const float*)d_in[18];
    const float* s6g  = (const float*)d_in[19];
    const float* gfW1 = (const float*)d_in[20];
    const float* gfb1 = (const float*)d_in[21];
    const float* gfW2 = (const float*)d_in[22];
    const float* gfb2 = (const float*)d_in[23];
    const float* gfg  = (const float*)d_in[24];
    const float* Wg   = (const float*)d_in[25];
    const float* mW1  = (const float*)d_in[26];
    const float* mb1  = (const float*)d_in[27];
    const float* mW2  = (const float*)d_in[28];
    const float* mb2  = (const float*)d_in[29];
    float* out = (float*)d_out;

    float *pP, *pXI, *pDelta, *pB, *pC, *pY, *pYO, *pG1, *pG2;
    cudaGetSymbolAddress((void**)&pP,     g_P);
    cudaGetSymbolAddress((void**)&pXI,    g_XI);
    cudaGetSymbolAddress((void**)&pDelta, g_delta);
    cudaGetSymbolAddress((void**)&pB,     g_Bmat);
    cudaGetSymbolAddress((void**)&pC,     g_Cmat);
    cudaGetSymbolAddress((void**)&pY,     g_y);
    cudaGetSymbolAddress((void**)&pYO,    g_yo);
    cudaGetSymbolAddress((void**)&pG1,    g_g1);
    cudaGetSymbolAddress((void**)&pG2,    g_g2);

    // grid = (M/128, N/128): M on x so concurrent CTAs share W column tiles
    // 1) P = x @ Wp + bp  [1024 x 2048]
    tgemm_kernel<0><<<dim3(8, 16), 256>>>(x, Wp, bp, pP, BT, 2048, 1024);
    // 2) XI = x @ Win + bin  [1024 x 2048]
    tgemm_kernel<0><<<dim3(8, 16), 256>>>(x, Win, bin, pXI, BT, 2048, 1024);
    // 3) rotary
    rotary_kernel<<<BT, 256>>>(sinp, cosp);
    // 4) dwconv + gate + rms
    glcm_kernel<<<BT, 256>>>(Wdw, bdw, glg);
    // 5) delta = softplus(XI @ Wd + bd)  [1024 x 1024], K=2048
    tgemm_kernel<1><<<dim3(8, 8), 256>>>(pXI, Wd, bd, pDelta, BT, 1024, 2048);
    // 6) Bm = XI @ WB + bB  [1024 x 16384], K=2048
    tgemm_kernel<0><<<dim3(8, 128), 256>>>(pXI, WB, bB, pB, BT, 16384, 2048);
    // 7) Cm = XI @ WC + bC
    tgemm_kernel<0><<<dim3(8, 128), 256>>>(pXI, WC, bC, pC, BT, 16384, 2048);
    // 8) scan
    scan_kernel<<<128, 256>>>(Alog);
    // 9) yo = y @ Wout + bout ; rms
    tgemm_kernel<0><<<dim3(8, 8), 256>>>(pY, Wout, bout, pYO, BT, 1024, 1024);
    rms_kernel<<<BT, 256>>>(s6g);
    // 10) gates
    tgemm_kernel<2><<<dim3(8, 8), 256>>>(x, gfW1, gfb1, pG1, BT, 1024, 1024);
    tgemm_kernel<2><<<dim3(8, 8), 256>>>(x, gfW2, gfb2, pG2, BT, 1024, 1024);
    // 11) combine
    combine_kernel<<<BT, 256>>>(x, gfg);
    // 12) routing
    zero_cnt_kernel<<<1, 32>>>();
    route_kernel<<<128, 256>>>(Wg);
    // 13) expert FFN phase 1 (silu), N=4096
    moe_tgemm_kernel<1><<<dim3(16, 32, 16), 256>>>(mW1, mb1);
    // 14) expert FFN phase 2 (weighted), N=1024
    moe_tgemm_kernel<2><<<dim3(16, 8, 16), 256>>>(mW2, mb2);
    // 15) final
    final_kernel<<<4096, 256>>>(out);
}

// round 9
// speedup vs baseline: 3.4034x; 1.1526x over previous
#include <cuda_runtime.h>
#include <cuda_bf16.h>
#include <math.h>
#include <stdint.h>

// ---------------- constants ----------------
constexpr int E_  = 16;
constexpr int T_  = 512;
constexpr int BT  = 1024;   // B*T
constexpr float EPS_ = 1e-8f;

// ---------------- f32 scratch ----------------
__device__ float g_P    [BT * 2048];
__device__ float g_XI   [BT * 2048];
__device__ float g_XR   [BT * 1024];
__device__ float g_glcm [BT * 1024];
__device__ float g_delta[BT * 1024];
__device__ float g_Bmat [BT * 16384];
__device__ float g_Cmat [BT * 16384];
__device__ float g_y    [BT * 1024];
__device__ float g_yo   [BT * 1024];
__device__ float g_s6   [BT * 1024];
__device__ float g_g1   [BT * 1024];
__device__ float g_g2   [BT * 1024];
__device__ float g_h    [BT * 1024];
__device__ float g_e1   [2 * BT * 4096];
__device__ float g_e2   [2 * BT * 1024];
__device__ int   g_cnt  [E_];
__device__ int   g_list [E_ * 2048];
__device__ float g_w    [2 * BT];

// ---------------- bf16 hi/lo mirrors (activations + weights, [K,N] layout kept) ----------------
__device__ __nv_bfloat16 g_xh [BT * 1024], g_xl [BT * 1024];
__device__ __nv_bfloat16 g_XIh[BT * 2048], g_XIl[BT * 2048];
__device__ __nv_bfloat16 g_yh [BT * 1024], g_yl [BT * 1024];
__device__ __nv_bfloat16 g_WpH [1024 * 2048], g_WpL [1024 * 2048];
__device__ __nv_bfloat16 g_WinH[1024 * 2048], g_WinL[1024 * 2048];
__device__ __nv_bfloat16 g_WdH [2048 * 1024], g_WdL [2048 * 1024];
__device__ __nv_bfloat16 g_WBH [2048UL * 16384], g_WBL [2048UL * 16384];
__device__ __nv_bfloat16 g_WCH [2048UL * 16384], g_WCL [2048UL * 16384];
__device__ __nv_bfloat16 g_WoH [1024 * 1024], g_WoL [1024 * 1024];
__device__ __nv_bfloat16 g_G1H [1024 * 1024], g_G1L [1024 * 1024];
__device__ __nv_bfloat16 g_G2H [1024 * 1024], g_G2L [1024 * 1024];

// ---------------- helpers ----------------
__device__ __forceinline__ float sigmoidf_(float x) { return 1.f / (1.f + expf(-x)); }

__device__ __forceinline__ float block_sum256(float v) {
    __shared__ float sh[8];
    int lane = threadIdx.x & 31, w = threadIdx.x >> 5;
#pragma unroll
    for (int o = 16; o; o >>= 1) v += __shfl_xor_sync(0xffffffffu, v, o);
    if (lane == 0) sh[w] = v;
    __syncthreads();
    float s = 0.f;
#pragma unroll
    for (int i = 0; i < 8; i++) s += sh[i];
    return s;
}

__device__ __forceinline__ uint32_t smem_u32(const void* p) {
    return (uint32_t)__cvta_generic_to_shared(p);
}

__device__ __forceinline__ void ldsm_x4(uint32_t& r0, uint32_t& r1, uint32_t& r2, uint32_t& r3, uint32_t addr) {
    asm volatile("ldmatrix.sync.aligned.m8n8.x4.shared.b16 {%0,%1,%2,%3}, [%4];"
        : "=r"(r0), "=r"(r1), "=r"(r2), "=r"(r3) : "r"(addr));
}
__device__ __forceinline__ void ldsm_x4_t(uint32_t& r0, uint32_t& r1, uint32_t& r2, uint32_t& r3, uint32_t addr) {
    asm volatile("ldmatrix.sync.aligned.m8n8.x4.trans.shared.b16 {%0,%1,%2,%3}, [%4];"
        : "=r"(r0), "=r"(r1), "=r"(r2), "=r"(r3) : "r"(addr));
}
__device__ __forceinline__ void mma_bf16(float* c, const uint32_t* a, const uint32_t* b) {
    asm volatile("mma.sync.aligned.m16n8k16.row.col.f32.bf16.bf16.f32 "
        "{%0,%1,%2,%3}, {%4,%5,%6,%7}, {%8,%9}, {%0,%1,%2,%3};"
        : "+f"(c[0]), "+f"(c[1]), "+f"(c[2]), "+f"(c[3])
        : "r"(a[0]), "r"(a[1]), "r"(a[2]), "r"(a[3]), "r"(b[0]), "r"(b[1]));
}
__device__ __forceinline__ void cvt_split16(const float* v, uint32_t* hi, uint32_t* lo) {
#pragma unroll
    for (int i = 0; i < 8; i++) {
        float x0 = v[2 * i], x1 = v[2 * i + 1];
        __nv_bfloat16 h0 = __float2bfloat16(x0), h1 = __float2bfloat16(x1);
        float r0 = x0 - __bfloat162float(h0), r1 = x1 - __bfloat162float(h1);
        __nv_bfloat16 l0 = __float2bfloat16(r0), l1 = __float2bfloat16(r1);
        hi[i] = ((uint32_t)__bfloat16_as_ushort(h1) << 16) | __bfloat16_as_ushort(h0);
        lo[i] = ((uint32_t)__bfloat16_as_ushort(l1) << 16) | __bfloat16_as_ushort(l0);
    }
}

__device__ __forceinline__ void cp16(uint32_t dst, const void* src) {
    asm volatile("cp.async.cg.shared.global [%0], [%1], 16;" :: "r"(dst), "l"(src));
}
#define CP_COMMIT() asm volatile("cp.async.commit_group;" ::: "memory")
#define CP_WAIT1()  asm volatile("cp.async.wait_group 1;" ::: "memory")

// ============================================================================
// Dense GEMM, legacy mma.sync, pre-split bf16 operands, cp.async 2-stage pipe.
// C[M,N] = A[M,K] @ W[K,N] + bias.  A: [M,K] bf16 hi/lo.  W: [K,N] bf16 hi/lo.
// CTA 128x128, KTILE 32, 256 threads = 8 warps (2m x 4n), warp 64x32.
// smem per stage: A 128x40h x2 planes (10240B ea... 20480), B 32x136h x2 (17408).
// ============================================================================
constexpr int AP = 10240;            // bytes per A plane (128*40*2)
constexpr int BP = 8704;             // bytes per B plane (32*136*2)
constexpr int STG = 2 * AP + 2 * BP; // 37888 per stage
constexpr int DSMEM = 2 * STG;       // 75776

template <int EPI, bool BOUT>   // EPI: 0 none, 1 softplus, 2 sigmoid
__global__ __launch_bounds__(256)
void mma_gemm(const __nv_bfloat16* __restrict__ Ah, const __nv_bfloat16* __restrict__ Al,
              const __nv_bfloat16* __restrict__ Wh, const __nv_bfloat16* __restrict__ Wl,
              const float* __restrict__ bias, float* __restrict__ C,
              __nv_bfloat16* __restrict__ Ch, __nv_bfloat16* __restrict__ Cl,
              int Ntot, int K) {
    extern __shared__ char smem[];
    const uint32_t sb = smem_u32(smem);

    const int tid = threadIdx.x;
    const int warp = tid >> 5, lane = tid & 31;
    const int wm = warp & 1, wn = warp >> 1;
    const int mBase = blockIdx.x * 128, nBase = blockIdx.y * 128;
    const int wmBase = wm * 64, wnBase = wn * 32;

    // loader chunk mapping
    // A: chunk c (0..511)/plane: row=c>>2, c4=c&3 ; 2 chunks per thread per plane
    // B: chunk c (0..511)/plane: row=c>>4, c16=c&15
    const int S = K >> 5;

    auto load_stage = [&](int s, int b) {
        const int k0 = s << 5;
        const uint32_t base = sb + b * STG;
#pragma unroll
        for (int i = 0; i < 2; i++) {
            int c = i * 256 + tid;
            int r = c >> 2, c4 = c & 3;
            uint32_t dst = base + (uint32_t)(r * 80 + c4 * 16);
            const __nv_bfloat16* srcH = Ah + (size_t)(mBase + r) * K + k0 + c4 * 8;
            const __nv_bfloat16* srcL = Al + (size_t)(mBase + r) * K + k0 + c4 * 8;
            cp16(dst, srcH);
            cp16(dst + AP, srcL);
        }
#pragma unroll
        for (int i = 0; i < 2; i++) {
            int c = i * 256 + tid;
            int r = c >> 4, c16 = c & 15;
            uint32_t dst = base + 2 * AP + (uint32_t)(r * 272 + c16 * 16);
            const __nv_bfloat16* srcH = Wh + (size_t)(k0 + r) * Ntot + nBase + c16 * 8;
            const __nv_bfloat16* srcL = Wl + (size_t)(k0 + r) * Ntot + nBase + c16 * 8;
            cp16(dst, srcH);
            cp16(dst + BP, srcL);
        }
    };

    float acc[4][4][4] = {};

    const int lrow = lane & 15;
    const int lcolB = ((lane >> 4) << 3) * 2;   // byte offset of ldmatrix column chunk

    load_stage(0, 0); CP_COMMIT();
    load_stage(1, 1); CP_COMMIT();

    for (int s = 0; s < S; s++) {
        const int b = s & 1;
        CP_WAIT1();
        __syncthreads();

        const uint32_t base = sb + b * STG;
        const uint32_t aH = base + (uint32_t)((wmBase + lrow) * 80) + lcolB;
        const uint32_t aL = aH + AP;
        const uint32_t bH = base + 2 * AP + (uint32_t)(lrow * 272) + (uint32_t)(wnBase * 2) + lcolB;
        const uint32_t bL = bH + BP;

#pragma unroll
        for (int chunk = 0; chunk < 2; chunk++) {
            uint32_t Afh[4][4], Afl[4][4], Bfh[4][2], Bfl[4][2];
#pragma unroll
            for (int mi = 0; mi < 4; mi++) {
                ldsm_x4(Afh[mi][0], Afh[mi][1], Afh[mi][2], Afh[mi][3],
                        aH + mi * (16 * 80) + chunk * 32);
                ldsm_x4(Afl[mi][0], Afl[mi][1], Afl[mi][2], Afl[mi][3],
                        aL + mi * (16 * 80) + chunk * 32);
            }
#pragma unroll
            for (int g = 0; g < 2; g++) {
                uint32_t r0, r1, r2, r3;
                ldsm_x4_t(r0, r1, r2, r3, bH + chunk * (16 * 272) + g * 32);
                Bfh[2 * g][0] = r0; Bfh[2 * g][1] = r1; Bfh[2 * g + 1][0] = r2; Bfh[2 * g + 1][1] = r3;
                ldsm_x4_t(r0, r1, r2, r3, bL + chunk * (16 * 272) + g * 32);
                Bfl[2 * g][0] = r0; Bfl[2 * g][1] = r1; Bfl[2 * g + 1][0] = r2; Bfl[2 * g + 1][1] = r3;
            }
#pragma unroll
            for (int mi = 0; mi < 4; mi++)
#pragma unroll
                for (int ni = 0; ni < 4; ni++) {
                    mma_bf16(acc[mi][ni], Afh[mi], Bfh[ni]);
                    mma_bf16(acc[mi][ni], Afh[mi], Bfl[ni]);
                    mma_bf16(acc[mi][ni], Afl[mi], Bfh[ni]);
                }
        }
        __syncthreads();
        if (s + 2 < S) load_stage(s + 2, b);
        CP_COMMIT();
    }

    // epilogue
    const int lr = lane >> 2, lc = (lane & 3) * 2;
#pragma unroll
    for (int mi = 0; mi < 4; mi++) {
        size_t row0 = (size_t)(mBase + wmBase + mi * 16 + lr);
#pragma unroll
        for (int ni = 0; ni < 4; ni++) {
            int col = nBase + wnBase + ni * 8 + lc;
            float b0 = bias[col], b1 = bias[col + 1];
            float v[4] = {acc[mi][ni][0] + b0, acc[mi][ni][1] + b1,
                          acc[mi][ni][2] + b0, acc[mi][ni][3] + b1};
#pragma unroll
            for (int q = 0; q < 4; q++) {
                if (EPI == 1) v[q] = fmaxf(v[q], 0.f) + log1pf(expf(-fabsf(v[q])));
                else if (EPI == 2) v[q] = sigmoidf_(v[q]);
            }
            size_t i0 = row0 * Ntot + col;
            size_t i1 = (row0 + 8) * Ntot + col;
            *(float2*)(C + i0) = make_float2(v[0], v[1]);
            *(float2*)(C + i1) = make_float2(v[2], v[3]);
            if (BOUT) {
                __nv_bfloat16 h0 = __float2bfloat16(v[0]), h1 = __float2bfloat16(v[1]);
                __nv_bfloat16 h2 = __float2bfloat16(v[2]), h3 = __float2bfloat16(v[3]);
                Ch[i0] = h0; Ch[i0 + 1] = h1; Ch[i1] = h2; Ch[i1 + 1] = h3;
                Cl[i0]     = __float2bfloat16(v[0] - __bfloat162float(h0));
                Cl[i0 + 1] = __float2bfloat16(v[1] - __bfloat162float(h1));
                Cl[i1]     = __float2bfloat16(v[2] - __bfloat162float(h2));
                Cl[i1 + 1] = __float2bfloat16(v[3] - __bfloat162float(h3));
            }
        }
    }
}

// ---------------- elementwise f32 -> bf16 hi/lo split ----------------
__global__ __launch_bounds__(256)
void convw_kernel(const float* __restrict__ W, __nv_bfloat16* __restrict__ H,
                  __nv_bfloat16* __restrict__ L) {
    size_t i = ((size_t)blockIdx.x * 256 + threadIdx.x) * 4;
    float4 v = *(const float4*)(W + i);
    float a[4] = {v.x, v.y, v.z, v.w};
    __nv_bfloat16 hh[4], ll[4];
#pragma unroll
    for (int j = 0; j < 4; j++) {
        hh[j] = __float2bfloat16(a[j]);
        ll[j] = __float2bfloat16(a[j] - __bfloat162float(hh[j]));
    }
    *(uint64_t*)(H + i) = *(uint64_t*)hh;
    *(uint64_t*)(L + i) = *(uint64_t*)ll;
}

// ---------------- MoE gather-GEMM (legacy, f32 in-kernel convert) ----------------
constexpr int A_STR = 40;
constexpr int B_STR = 136;

template <int PHASE>
__global__ __launch_bounds__(256)
void moe_tgemm_kernel(const float* __restrict__ Wall, const float* __restrict__ ball) {
    constexpr int K = (PHASE == 1) ? 1024 : 4096;
    constexpr int N = (PHASE == 1) ? 4096 : 1024;
    const int e = blockIdx.z;
    const int mc = g_cnt[e];
    const int m0 = blockIdx.x * 128;
    if (m0 >= mc) return;
    const float* Asrc = (PHASE == 1) ? g_h : g_e1;
    float* Cd = (PHASE == 1) ? g_e1 : g_e2;
    const float* W = Wall + (size_t)e * K * N;
    const float* bias = ball + (size_t)e * N;

    __shared__ int rows[128];
    __shared__ __nv_bfloat16 sAh[128][A_STR];
    __shared__ __nv_bfloat16 sAl[128][A_STR];
    __shared__ __nv_bfloat16 sBh[32][B_STR];
    __shared__ __nv_bfloat16 sBl[32][B_STR];

    const int tid = threadIdx.x;
    const int warp = tid >> 5, lane = tid & 31;
    const int wm = warp & 1, wn = warp >> 1;
    const int nBase = blockIdx.y * 128;
    const int wmBase = wm * 64, wnBase = wn * 32;

    if (tid < 128) {
        int m = m0 + tid;
        rows[tid] = (m < mc) ? g_list[e * 2048 + m] : -1;
    }
    __syncthreads();

    const int arow = tid >> 1, acb = (tid & 1) * 16;
    const int brow = tid >> 3, bcb = (tid & 7) * 16;
    const int arid = rows[arow];
    const size_t srow = (PHASE == 1) ? (size_t)(arid >> 1) : (size_t)arid;

    const int lrow = lane & 15;
    const int lcol = (lane >> 4) << 3;
    const uint32_t aBaseH = smem_u32(&sAh[wmBase + lrow][lcol]);
    const uint32_t aBaseL = smem_u32(&sAl[wmBase + lrow][lcol]);
    const uint32_t bBaseH = smem_u32(&sBh[lrow][wnBase + lcol]);
    const uint32_t bBaseL = smem_u32(&sBl[lrow][wnBase + lcol]);

    float acc[4][4][4] = {};

    for (int k0 = 0; k0 < K; k0 += 32) {
        {
            float av[16];
            if (arid >= 0) {
                const float* ap = Asrc + srow * K + k0 + acb;
                *(float4*)&av[0]  = *(const float4*)(ap);
                *(float4*)&av[4]  = *(const float4*)(ap + 4);
                *(float4*)&av[8]  = *(const float4*)(ap + 8);
                *(float4*)&av[12] = *(const float4*)(ap + 12);
            } else {
#pragma unroll
                for (int i = 0; i < 16; i++) av[i] = 0.f;
            }
            uint32_t hi[8], lo[8];
            cvt_split16(av, hi, lo);
            *(uint4*)&sAh[arow][acb]     = *(uint4*)&hi[0];
            *(uint4*)&sAh[arow][acb + 8] = *(uint4*)&hi[4];
            *(uint4*)&sAl[arow][acb]     = *(uint4*)&lo[0];
            *(uint4*)&sAl[arow][acb + 8] = *(uint4*)&lo[4];
        }
        {
            const float* bp = W + (size_t)(k0 + brow) * N + nBase + bcb;
            float bv[16];
            *(float4*)&bv[0]  = *(const float4*)(bp);
            *(float4*)&bv[4]  = *(const float4*)(bp + 4);
            *(float4*)&bv[8]  = *(const float4*)(bp + 8);
            *(float4*)&bv[12] = *(const float4*)(bp + 12);
            uint32_t hi[8], lo[8];
            cvt_split16(bv, hi, lo);
            *(uint4*)&sBh[brow][bcb]     = *(uint4*)&hi[0];
            *(uint4*)&sBh[brow][bcb + 8] = *(uint4*)&hi[4];
            *(uint4*)&sBl[brow][bcb]     = *(uint4*)&lo[0];
            *(uint4*)&sBl[brow][bcb + 8] = *(uint4*)&lo[4];
        }
        __syncthreads();

#pragma unroll
        for (int chunk = 0; chunk < 2; chunk++) {
            uint32_t Ah[4][4], Al[4][4], Bh[4][2], Bl[4][2];
#pragma unroll
            for (int mi = 0; mi < 4; mi++) {
                ldsm_x4(Ah[mi][0], Ah[mi][1], Ah[mi][2], Ah[mi][3],
                        aBaseH + mi * (16 * A_STR * 2) + chunk * 32);
                ldsm_x4(Al[mi][0], Al[mi][1], Al[mi][2], Al[mi][3],
                        aBaseL + mi * (16 * A_STR * 2) + chunk * 32);
            }
#pragma unroll
            for (int g = 0; g < 2; g++) {
                uint32_t r0, r1, r2, r3;
                ldsm_x4_t(r0, r1, r2, r3, bBaseH + chunk * (16 * B_STR * 2) + g * 32);
                Bh[2 * g][0] = r0; Bh[2 * g][1] = r1; Bh[2 * g + 1][0] = r2; Bh[2 * g + 1][1] = r3;
                ldsm_x4_t(r0, r1, r2, r3, bBaseL + chunk * (16 * B_STR * 2) + g * 32);
                Bl[2 * g][0] = r0; Bl[2 * g][1] = r1; Bl[2 * g + 1][0] = r2; Bl[2 * g + 1][1] = r3;
            }
#pragma unroll
            for (int mi = 0; mi < 4; mi++)
#pragma unroll
                for (int ni = 0; ni < 4; ni++) {
                    mma_bf16(acc[mi][ni], Ah[mi], Bh[ni]);
                    mma_bf16(acc[mi][ni], Ah[mi], Bl[ni]);
                    mma_bf16(acc[mi][ni], Al[mi], Bh[ni]);
                }
        }
        __syncthreads();
    }

    const int lr = lane >> 2, lc = (lane & 3) * 2;
#pragma unroll
    for (int mi = 0; mi < 4; mi++) {
        int a0 = rows[wmBase + mi * 16 + lr];
        int a1 = rows[wmBase + mi * 16 + lr + 8];
        float w0 = (PHASE == 2 && a0 >= 0) ? g_w[a0] : 1.f;
        float w1 = (PHASE == 2 && a1 >= 0) ? g_w[a1] : 1.f;
#pragma unroll
        for (int ni = 0; ni < 4; ni++) {
            int col = nBase + wnBase + ni * 8 + lc;
            float b0 = bias[col], b1 = bias[col + 1];
            float v00 = acc[mi][ni][0] + b0, v01 = acc[mi][ni][1] + b1;
            float v10 = acc[mi][ni][2] + b0, v11 = acc[mi][ni][3] + b1;
            if (PHASE == 1) {
                v00 *= sigmoidf_(v00); v01 *= sigmoidf_(v01);
                v10 *= sigmoidf_(v10); v11 *= sigmoidf_(v11);
            } else {
                v00 *= w0; v01 *= w0; v10 *= w1; v11 *= w1;
            }
            if (a0 >= 0) *(float2*)(Cd + (size_t)a0 * N + col) = make_float2(v00, v01);
            if (a1 >= 0) *(float2*)(Cd + (size_t)a1 * N + col) = make_float2(v10, v11);
        }
    }
}

// ---------------- x -> bf16 hi/lo ----------------
__global__ void convx_kernel(const float* __restrict__ x) {
    int i = (blockIdx.x * 256 + threadIdx.x) * 4;
    float4 v = *(const float4*)(x + i);
    float a[4] = {v.x, v.y, v.z, v.w};
#pragma unroll
    for (int j = 0; j < 4; j++) {
        __nv_bfloat16 h = __float2bfloat16(a[j]);
        g_xh[i + j] = h;
        g_xl[i + j] = __float2bfloat16(a[j] - __bfloat162float(h));
    }
}

// ---------------- rotary ----------------
__global__ void rotary_kernel(const float* __restrict__ sinp, const float* __restrict__ cosp) {
    int r = blockIdx.x;
    int t = r & (T_ - 1);
    const float* pr = g_P + (size_t)r * 2048;
    float* xr = g_XR + (size_t)r * 1024;
    for (int i = threadIdx.x; i < 512; i += 256) {
        float c = cosp[t * 512 + i], s = sinp[t * 512 + i];
        float a0 = pr[2 * i], a1 = pr[2 * i + 1];
        xr[2 * i]     = a0 * c - a1 * s;
        xr[2 * i + 1] = a0 * s + a1 * c;
    }
}

// ---------------- dwconv + gate + RMS -> glcm ----------------
__global__ void glcm_kernel(const float* __restrict__ Wdw, const float* __restrict__ bdw,
                            const float* __restrict__ gg) {
    int r = blockIdx.x;
    int b = r >> 9, t = r & 511;
    float vals[4];
    float ss = 0.f;
#pragma unroll
    for (int j = 0; j < 4; j++) {
        int d = threadIdx.x + j * 256;
        float conv = bdw[d];
#pragma unroll
        for (int k = 0; k < 7; k++) {
            int tt = t + k - 3;
            if (tt >= 0 && tt < T_)
                conv += g_XR[(size_t)(b * T_ + tt) * 1024 + d] * Wdw[k * 1024 + d];
        }
        float xb = g_P[(size_t)r * 2048 + 1024 + d];
        float v = conv * sigmoidf_(conv) * sigmoidf_(xb);
        vals[j] = v;
        ss += v * v;
    }
    ss = block_sum256(ss);
    float inv = 1.f / sqrtf(ss * (1.f / 1024.f) + EPS_);
#pragma unroll
    for (int j = 0; j < 4; j++) {
        int d = threadIdx.x + j * 256;
        g_glcm[(size_t)r * 1024 + d] = gg[d] * vals[j] * inv;
    }
}

// ---------------- sequential S6 scan (also emits y bf16 hi/lo) ----------------
__global__ void scan_kernel(const float* __restrict__ Alog) {
    int gw = (blockIdx.x * blockDim.x + threadIdx.x) >> 5;
    int lane = threadIdx.x & 31;
    int b = gw >> 9;
    int spair = gw & 511;
    int half = lane >> 4, n = lane & 15;
    int s = spair * 2 + half;
    float A = -expf(Alog[s * 16 + n]);
    float h = 0.f;
    const int base_r = b * T_;
    for (int t = 0; t < T_; t++) {
        int r = base_r + t;
        float d  = g_delta[(size_t)r * 1024 + s];
        float u  = g_XI[(size_t)r * 2048 + s];
        float Bv = g_Bmat[(size_t)r * 16384 + s * 16 + n];
        float Cv = g_Cmat[(size_t)r * 16384 + s * 16 + n];
        h = expf(d * A) * h + (d * u) * Bv;
        float p = h * Cv;
        p += __shfl_xor_sync(0xffffffffu, p, 1);
        p += __shfl_xor_sync(0xffffffffu, p, 2);
        p += __shfl_xor_sync(0xffffffffu, p, 4);
        p += __shfl_xor_sync(0xffffffffu, p, 8);
        if (n == 0) {
            size_t idx = (size_t)r * 1024 + s;
            g_y[idx] = p;
            __nv_bfloat16 hh = __float2bfloat16(p);
            g_yh[idx] = hh;
            g_yl[idx] = __float2bfloat16(p - __bfloat162float(hh));
        }
    }
}

// ---------------- RMS ----------------
__global__ void rms_kernel(const float* __restrict__ gg) {
    int r = blockIdx.x;
    const float* xin = g_yo + (size_t)r * 1024;
    float vals[4];
    float ss = 0.f;
#pragma unroll
    for (int j = 0; j < 4; j++) {
        int d = threadIdx.x + j * 256;
        float v = xin[d];
        vals[j] = v;
        ss += v * v;
    }
    ss = block_sum256(ss);
    float inv = 1.f / sqrtf(ss * (1.f / 1024.f) + EPS_);
#pragma unroll
    for (int j = 0; j < 4; j++) {
        int d = threadIdx.x + j * 256;
        g_s6[(size_t)r * 1024 + d] = gg[d] * vals[j] * inv;
    }
}

// ---------------- combine ----------------
__global__ void combine_kernel(const float* __restrict__ x, const float* __restrict__ gfg) {
    int r = blockIdx.x;
    float vals[4];
    float ss = 0.f;
#pragma unroll
    for (int j = 0; j < 4; j++) {
        int d = threadIdx.x + j * 256;
        size_t idx = (size_t)r * 1024 + d;
        float v = g_g1[idx] * g_s6[idx] + g_g2[idx] * g_glcm[idx];
        vals[j] = v;
        ss += v * v;
    }
    ss = block_sum256(ss);
    float inv = 1.f / sqrtf(ss * (1.f / 1024.f) + EPS_);
#pragma unroll
    for (int j = 0; j < 4; j++) {
        int d = threadIdx.x + j * 256;
        size_t idx = (size_t)r * 1024 + d;
        g_h[idx] = x[idx] + gfg[d] * vals[j] * inv;
    }
}

// ---------------- MoE routing ----------------
__global__ void zero_cnt_kernel() {
    if (threadIdx.x < E_) g_cnt[threadIdx.x] = 0;
}

__global__ void route_kernel(const float* __restrict__ Wg) {
    int warp = threadIdx.x >> 5, lane = threadIdx.x & 31;
    int token = blockIdx.x * 8 + warp;
    float acc[16];
#pragma unroll
    for (int e = 0; e < 16; e++) acc[e] = 0.f;
    const float* hrow = g_h + (size_t)token * 1024;
    for (int d = lane; d < 1024; d += 32) {
        float xv = hrow[d];
#pragma unroll
        for (int e = 0; e < 16; e++) acc[e] += xv * Wg[d * 16 + e];
    }
#pragma unroll
    for (int e = 0; e < 16; e++) {
#pragma unroll
        for (int o = 16; o; o >>= 1) acc[e] += __shfl_xor_sync(0xffffffffu, acc[e], o);
    }
    if (lane == 0) {
        float v0 = -1e30f; int i0 = 0;
#pragma unroll
        for (int e = 0; e < 16; e++) if (acc[e] > v0) { v0 = acc[e]; i0 = e; }
        float v1 = -1e30f; int i1 = 0;
#pragma unroll
        for (int e = 0; e < 16; e++) if (e != i0 && acc[e] > v1) { v1 = acc[e]; i1 = e; }
        float w0 = 1.f / (1.f + expf(v1 - v0));
        g_w[token * 2]     = w0;
        g_w[token * 2 + 1] = 1.f - w0;
        int p0 = atomicAdd(&g_cnt[i0], 1);
        g_list[i0 * 2048 + p0] = token * 2;
        int p1 = atomicAdd(&g_cnt[i1], 1);
        g_list[i1 * 2048 + p1] = token * 2 + 1;
    }
}

// ---------------- final ----------------
__global__ void final_kernel(float* __restrict__ out) {
    int idx = blockIdx.x * 256 + threadIdx.x;
    int r = idx >> 10, d = idx & 1023;
    out[idx] = g_h[idx] + g_e2[(size_t)r * 2048 + d] + g_e2[(size_t)r * 2048 + 1024 + d];
}

// ---------------- launch ----------------
extern "C" void kernel_launch(void* const* d_in, const int* /*in_sizes*/, int /*n_in*/,
                              void* d_out, int /*out_size*/) {
    const float* x    = (const float*)d_in[0];
    const float* sinp = (const float*)d_in[1];
    const float* cosp = (const float*)d_in[2];
    const float* Wp   = (const float*)d_in[3];
    const float* bp   = (const float*)d_in[4];
    const float* Wdw  = (const float*)d_in[5];
    const float* bdw  = (const float*)d_in[6];
    const float* glg  = (const float*)d_in[7];
    const float* Win  = (const float*)d_in[8];
    const float* bin  = (const float*)d_in[9];
    const float* Wd   = (const float*)d_in[10];
    const float* bd   = (const float*)d_in[11];
    const float* WB   = (const float*)d_in[12];
    const float* bB   = (const float*)d_in[13];
    const float* WC   = (const float*)d_in[14];
    const float* bC   = (const float*)d_in[15];
    const float* Alog = (const float*)d_in[16];
    const float* Wout = (const float*)d_in[17];
    const float* bout = (const float*)d_in[18];
    const float* s6g  = (const float*)d_in[19];
    const float* gfW1 = (const float*)d_in[20];
    const float* gfb1 = (const float*)d_in[21];
    const float* gfW2 = (const float*)d_in[22];
    const float* gfb2 = (const float*)d_in[23];
    const float* gfg  = (const float*)d_in[24];
    const float* Wg   = (const float*)d_in[25];
    const float* mW1  = (const float*)d_in[26];
    const float* mb1  = (const float*)d_in[27];
    const float* mW2  = (const float*)d_in[28];
    const float* mb2  = (const float*)d_in[29];
    float* out = (float*)d_out;

    cudaFuncSetAttribute(mma_gemm<0, false>, cudaFuncAttributeMaxDynamicSharedMemorySize, DSMEM);
    cudaFuncSetAttribute(mma_gemm<0, true>,  cudaFuncAttributeMaxDynamicSharedMemorySize, DSMEM);
    cudaFuncSetAttribute(mma_gemm<1, false>, cudaFuncAttributeMaxDynamicSharedMemorySize, DSMEM);
    cudaFuncSetAttribute(mma_gemm<2, false>, cudaFuncAttributeMaxDynamicSharedMemorySize, DSMEM);

    float *pP, *pXI, *pDelta, *pB, *pC, *pYO;
    cudaGetSymbolAddress((void**)&pP,     g_P);
    cudaGetSymbolAddress((void**)&pXI,    g_XI);
    cudaGetSymbolAddress((void**)&pDelta, g_delta);
    cudaGetSymbolAddress((void**)&pB,     g_Bmat);
    cudaGetSymbolAddress((void**)&pC,     g_Cmat);
    cudaGetSymbolAddress((void**)&pYO,    g_yo);
    float *pG1, *pG2;
    cudaGetSymbolAddress((void**)&pG1,    g_g1);
    cudaGetSymbolAddress((void**)&pG2,    g_g2);

    __nv_bfloat16 *xh, *xl, *XIh, *XIl, *yh, *yl;
    __nv_bfloat16 *WpH, *WpL, *WinH, *WinL, *WdH, *WdL, *WBH, *WBL, *WCH, *WCL;
    __nv_bfloat16 *WoH, *WoL, *G1H, *G1L, *G2H, *G2L;
    cudaGetSymbolAddress((void**)&xh,  g_xh);  cudaGetSymbolAddress((void**)&xl,  g_xl);
    cudaGetSymbolAddress((void**)&XIh, g_XIh); cudaGetSymbolAddress((void**)&XIl, g_XIl);
    cudaGetSymbolAddress((void**)&yh,  g_yh);  cudaGetSymbolAddress((void**)&yl,  g_yl);
    cudaGetSymbolAddress((void**)&WpH, g_WpH); cudaGetSymbolAddress((void**)&WpL, g_WpL);
    cudaGetSymbolAddress((void**)&WinH,g_WinH);cudaGetSymbolAddress((void**)&WinL,g_WinL);
    cudaGetSymbolAddress((void**)&WdH, g_WdH); cudaGetSymbolAddress((void**)&WdL, g_WdL);
    cudaGetSymbolAddress((void**)&WBH, g_WBH); cudaGetSymbolAddress((void**)&WBL, g_WBL);
    cudaGetSymbolAddress((void**)&WCH, g_WCH); cudaGetSymbolAddress((void**)&WCL, g_WCL);
    cudaGetSymbolAddress((void**)&WoH, g_WoH); cudaGetSymbolAddress((void**)&WoL, g_WoL);
    cudaGetSymbolAddress((void**)&G1H, g_G1H); cudaGetSymbolAddress((void**)&G1L, g_G1L);
    cudaGetSymbolAddress((void**)&G2H, g_G2H); cudaGetSymbolAddress((void**)&G2L, g_G2L);

    // 0) operand pre-splits (elementwise, layout preserved)
    convx_kernel<<<1024, 256>>>(x);
    convw_kernel<<<(1024 * 2048) / 1024, 256>>>(Wp,   WpH,  WpL);
    convw_kernel<<<(1024 * 2048) / 1024, 256>>>(Win,  WinH, WinL);
    convw_kernel<<<(2048 * 1024) / 1024, 256>>>(Wd,   WdH,  WdL);
    convw_kernel<<<(2048UL * 16384) / 1024, 256>>>(WB, WBH, WBL);
    convw_kernel<<<(2048UL * 16384) / 1024, 256>>>(WC, WCH, WCL);
    convw_kernel<<<(1024 * 1024) / 1024, 256>>>(Wout, WoH,  WoL);
    convw_kernel<<<(1024 * 1024) / 1024, 256>>>(gfW1, G1H,  G1L);
    convw_kernel<<<(1024 * 1024) / 1024, 256>>>(gfW2, G2H,  G2L);

    // grid (M/128, N/128): M on x so concurrent CTAs share W column tiles
    // 1) P = x @ Wp + bp
    mma_gemm<0, false><<<dim3(8, 16), 256, DSMEM>>>(xh, xl, WpH, WpL, bp, pP, nullptr, nullptr, 2048, 1024);
    // 2) XI = x @ Win + bin (emit bf16 mirrors)
    mma_gemm<0, true><<<dim3(8, 16), 256, DSMEM>>>(xh, xl, WinH, WinL, bin, pXI, XIh, XIl, 2048, 1024);
    // 3) rotary + glcm
    rotary_kernel<<<BT, 256>>>(sinp, cosp);
    glcm_kernel<<<BT, 256>>>(Wdw, bdw, glg);
    // 5) delta = softplus(XI @ Wd + bd)
    mma_gemm<1, false><<<dim3(8, 8), 256, DSMEM>>>(XIh, XIl, WdH, WdL, bd, pDelta, nullptr, nullptr, 1024, 2048);
    // 6/7) B, C projections
    mma_gemm<0, false><<<dim3(8, 128), 256, DSMEM>>>(XIh, XIl, WBH, WBL, bB, pB, nullptr, nullptr, 16384, 2048);
    mma_gemm<0, false><<<dim3(8, 128), 256, DSMEM>>>(XIh, XIl, WCH, WCL, bC, pC, nullptr, nullptr, 16384, 2048);
    // 8) scan
    scan_kernel<<<128, 256>>>(Alog);
    // 9) yo = y @ Wout + bout ; rms
    mma_gemm<0, false><<<dim3(8, 8), 256, DSMEM>>>(yh, yl, WoH, WoL, bout, pYO, nullptr, nullptr, 1024, 1024);
    rms_kernel<<<BT, 256>>>(s6g);
    // 10) gates
    mma_gemm<2, false><<<dim3(8, 8), 256, DSMEM>>>(xh, xl, G1H, G1L, gfb1, pG1, nullptr, nullptr, 1024, 1024);
    mma_gemm<2, false><<<dim3(8, 8), 256, DSMEM>>>(xh, xl, G2H, G2L, gfb2, pG2, nullptr, nullptr, 1024, 1024);
    // 11) combine
    combine_kernel<<<BT, 256>>>(x, gfg);
    // 12) routing
    zero_cnt_kernel<<<1, 32>>>();
    route_kernel<<<128, 256>>>(Wg);
    // 13/14) expert FFN
    moe_tgemm_kernel<1><<<dim3(16, 32, 16), 256>>>(mW1, mb1);
    moe_tgemm_kernel<2><<<dim3(16, 8, 16), 256>>>(mW2, mb2);
    // 15) final
    final_kernel<<<4096, 256>>>(out);
}

// round 10
// speedup vs baseline: 3.4426x; 1.0115x over previous
#include <cuda_runtime.h>
#include <cuda_bf16.h>
#include <math.h>
#include <stdint.h>

// ---------------- constants ----------------
constexpr int E_  = 16;
constexpr int T_  = 512;
constexpr int BT  = 1024;   // B*T
constexpr float EPS_ = 1e-8f;

// ---------------- f32 scratch ----------------
__device__ float g_P    [BT * 2048];
__device__ float g_XI   [BT * 2048];
__device__ float g_XR   [BT * 1024];
__device__ float g_glcm [BT * 1024];
__device__ float g_delta[BT * 1024];
__device__ float g_Bmat [BT * 16384];
__device__ float g_Cmat [BT * 16384];
__device__ float g_y    [BT * 1024];
__device__ float g_yo   [BT * 1024];
__device__ float g_s6   [BT * 1024];
__device__ float g_g1   [BT * 1024];
__device__ float g_g2   [BT * 1024];
__device__ float g_h    [BT * 1024];
__device__ float g_e1   [2 * BT * 4096];
__device__ float g_e2   [2 * BT * 1024];
__device__ int   g_cnt  [E_];
__device__ int   g_list [E_ * 2048];
__device__ float g_w    [2 * BT];

// ---------------- bf16 hi/lo activation mirrors ----------------
__device__ __nv_bfloat16 g_xh [BT * 1024], g_xl [BT * 1024];
__device__ __nv_bfloat16 g_XIh[BT * 2048], g_XIl[BT * 2048];
__device__ __nv_bfloat16 g_yh [BT * 1024], g_yl [BT * 1024];

// ---------------- helpers ----------------
__device__ __forceinline__ float sigmoidf_(float x) { return 1.f / (1.f + expf(-x)); }

__device__ __forceinline__ float block_sum256(float v) {
    __shared__ float sh[8];
    int lane = threadIdx.x & 31, w = threadIdx.x >> 5;
#pragma unroll
    for (int o = 16; o; o >>= 1) v += __shfl_xor_sync(0xffffffffu, v, o);
    if (lane == 0) sh[w] = v;
    __syncthreads();
    float s = 0.f;
#pragma unroll
    for (int i = 0; i < 8; i++) s += sh[i];
    return s;
}

__device__ __forceinline__ uint32_t smem_u32(const void* p) {
    return (uint32_t)__cvta_generic_to_shared(p);
}

__device__ __forceinline__ void ldsm_x4(uint32_t& r0, uint32_t& r1, uint32_t& r2, uint32_t& r3, uint32_t addr) {
    asm volatile("ldmatrix.sync.aligned.m8n8.x4.shared.b16 {%0,%1,%2,%3}, [%4];"
        : "=r"(r0), "=r"(r1), "=r"(r2), "=r"(r3) : "r"(addr));
}
__device__ __forceinline__ void ldsm_x4_t(uint32_t& r0, uint32_t& r1, uint32_t& r2, uint32_t& r3, uint32_t addr) {
    asm volatile("ldmatrix.sync.aligned.m8n8.x4.trans.shared.b16 {%0,%1,%2,%3}, [%4];"
        : "=r"(r0), "=r"(r1), "=r"(r2), "=r"(r3) : "r"(addr));
}
__device__ __forceinline__ void mma_bf16(float* c, const uint32_t* a, const uint32_t* b) {
    asm volatile("mma.sync.aligned.m16n8k16.row.col.f32.bf16.bf16.f32 "
        "{%0,%1,%2,%3}, {%4,%5,%6,%7}, {%8,%9}, {%0,%1,%2,%3};"
        : "+f"(c[0]), "+f"(c[1]), "+f"(c[2]), "+f"(c[3])
        : "r"(a[0]), "r"(a[1]), "r"(a[2]), "r"(a[3]), "r"(b[0]), "r"(b[1]));
}
__device__ __forceinline__ void cvt_split16(const float* v, uint32_t* hi, uint32_t* lo) {
#pragma unroll
    for (int i = 0; i < 8; i++) {
        float x0 = v[2 * i], x1 = v[2 * i + 1];
        __nv_bfloat16 h0 = __float2bfloat16(x0), h1 = __float2bfloat16(x1);
        float r0 = x0 - __bfloat162float(h0), r1 = x1 - __bfloat162float(h1);
        __nv_bfloat16 l0 = __float2bfloat16(r0), l1 = __float2bfloat16(r1);
        hi[i] = ((uint32_t)__bfloat16_as_ushort(h1) << 16) | __bfloat16_as_ushort(h0);
        lo[i] = ((uint32_t)__bfloat16_as_ushort(l1) << 16) | __bfloat16_as_ushort(l0);
    }
}

__device__ __forceinline__ void cp16(uint32_t dst, const void* src) {
    asm volatile("cp.async.cg.shared.global [%0], [%1], 16;" :: "r"(dst), "l"(src));
}
#define CP_COMMIT() asm volatile("cp.async.commit_group;" ::: "memory")
#define CP_WAIT1()  asm volatile("cp.async.wait_group 1;" ::: "memory")

// ============================================================================
// Dense GEMM: C[M,N] = A[M,K] @ W[K,N] + bias
// A: bf16 hi/lo mirrors (cp.async 2-stage pipe).
// W: raw f32, register-prefetched one stage ahead, split to bf16 hi/lo into
//    the same smem planes the compute path reads.
// CTA 128x128, KTILE 32, 256 threads = 8 warps (2m x 4n), warp 64x32.
// gridDim.z selects (W, bias, C) pair for merged launches; z==1 may emit
// bf16 hi/lo output mirrors (Ch/Cl non-null).
// ============================================================================
constexpr int AP = 10240;            // bytes per A plane (128*40*2)
constexpr int BP = 8704;             // bytes per B plane (32*136*2)
constexpr int STG = 2 * AP + 2 * BP; // 37888 per stage
constexpr int DSMEM = 2 * STG;       // 75776

template <int EPI>   // EPI: 0 none, 1 softplus, 2 sigmoid
__global__ __launch_bounds__(256)
void wgemm(const __nv_bfloat16* __restrict__ Ah, const __nv_bfloat16* __restrict__ Al,
           const float* __restrict__ W0, const float* __restrict__ W1,
           const float* __restrict__ b0, const float* __restrict__ b1,
           float* __restrict__ C0, float* __restrict__ C1,
           __nv_bfloat16* __restrict__ Ch, __nv_bfloat16* __restrict__ Cl,
           int Ntot, int K) {
    extern __shared__ char smem[];
    const uint32_t sb = smem_u32(smem);

    const int z = blockIdx.z;
    const float* __restrict__ W    = z ? W1 : W0;
    const float* __restrict__ bias = z ? b1 : b0;
    float* __restrict__ C          = z ? C1 : C0;
    const bool bout = (Ch != nullptr) && (z == 1);

    const int tid = threadIdx.x;
    const int warp = tid >> 5, lane = tid & 31;
    const int wm = warp & 1, wn = warp >> 1;
    const int mBase = blockIdx.x * 128, nBase = blockIdx.y * 128;
    const int wmBase = wm * 64, wnBase = wn * 32;

    const int S = K >> 5;

    // A loader (cp.async, hi+lo planes)
    auto load_A = [&](int s, int b) {
        const int k0 = s << 5;
        const uint32_t base = sb + b * STG;
#pragma unroll
        for (int i = 0; i < 2; i++) {
            int c = i * 256 + tid;
            int r = c >> 2, c4 = c & 3;
            uint32_t dst = base + (uint32_t)(r * 80 + c4 * 16);
            cp16(dst,      Ah + (size_t)(mBase + r) * K + k0 + c4 * 8);
            cp16(dst + AP, Al + (size_t)(mBase + r) * K + k0 + c4 * 8);
        }
    };

    // W loader: 16 f32 per thread (row = tid>>3, cols (tid&7)*16 .. +15)
    const int wr = tid >> 3, wc = (tid & 7) * 16;
    float wreg[16];
    auto ldg_W = [&](int s) {
        const float* src = W + (size_t)((s << 5) + wr) * Ntot + nBase + wc;
        *(float4*)&wreg[0]  = *(const float4*)(src);
        *(float4*)&wreg[4]  = *(const float4*)(src + 4);
        *(float4*)&wreg[8]  = *(const float4*)(src + 8);
        *(float4*)&wreg[12] = *(const float4*)(src + 12);
    };
    auto sts_W = [&](int b) {
        uint32_t hi[8], lo[8];
        cvt_split16(wreg, hi, lo);
        const uint32_t dst = sb + b * STG + 2 * AP + (uint32_t)(wr * 272 + wc * 2);
        *(uint4*)(smem + (dst - sb))          = *(uint4*)&hi[0];
        *(uint4*)(smem + (dst - sb) + 16)     = *(uint4*)&hi[4];
        *(uint4*)(smem + (dst - sb) + BP)     = *(uint4*)&lo[0];
        *(uint4*)(smem + (dst - sb) + BP + 16)= *(uint4*)&lo[4];
    };

    float acc[4][4][4] = {};

    const int lrow = lane & 15;
    const int lcolB = ((lane >> 4) << 3) * 2;

    ldg_W(0);
    load_A(0, 0); CP_COMMIT();
    load_A(1, 1); CP_COMMIT();

    for (int s = 0; s < S; s++) {
        const int b = s & 1;
        sts_W(b);                        // stage s W -> buffer b (safe: buffer b idle)
        if (s + 1 < S) ldg_W(s + 1);     // prefetch next W (consumed next iter)
        CP_WAIT1();
        __syncthreads();                 // A(b) + W(b) visible to all

        const uint32_t base = sb + b * STG;
        const uint32_t aH = base + (uint32_t)((wmBase + lrow) * 80) + lcolB;
        const uint32_t aL = aH + AP;
        const uint32_t bH = base + 2 * AP + (uint32_t)(lrow * 272) + (uint32_t)(wnBase * 2) + lcolB;
        const uint32_t bL = bH + BP;

#pragma unroll
        for (int chunk = 0; chunk < 2; chunk++) {
            uint32_t Afh[4][4], Afl[4][4], Bfh[4][2], Bfl[4][2];
#pragma unroll
            for (int mi = 0; mi < 4; mi++) {
                ldsm_x4(Afh[mi][0], Afh[mi][1], Afh[mi][2], Afh[mi][3],
                        aH + mi * (16 * 80) + chunk * 32);
                ldsm_x4(Afl[mi][0], Afl[mi][1], Afl[mi][2], Afl[mi][3],
                        aL + mi * (16 * 80) + chunk * 32);
            }
#pragma unroll
            for (int g = 0; g < 2; g++) {
                uint32_t r0, r1, r2, r3;
                ldsm_x4_t(r0, r1, r2, r3, bH + chunk * (16 * 272) + g * 32);
                Bfh[2 * g][0] = r0; Bfh[2 * g][1] = r1; Bfh[2 * g + 1][0] = r2; Bfh[2 * g + 1][1] = r3;
                ldsm_x4_t(r0, r1, r2, r3, bL + chunk * (16 * 272) + g * 32);
                Bfl[2 * g][0] = r0; Bfl[2 * g][1] = r1; Bfl[2 * g + 1][0] = r2; Bfl[2 * g + 1][1] = r3;
            }
#pragma unroll
            for (int mi = 0; mi < 4; mi++)
#pragma unroll
                for (int ni = 0; ni < 4; ni++) {
                    mma_bf16(acc[mi][ni], Afh[mi], Bfh[ni]);
                    mma_bf16(acc[mi][ni], Afh[mi], Bfl[ni]);
                    mma_bf16(acc[mi][ni], Afl[mi], Bfh[ni]);
                }
        }
        __syncthreads();
        if (s + 2 < S) load_A(s + 2, b);
        CP_COMMIT();
    }

    // epilogue
    const int lr = lane >> 2, lc = (lane & 3) * 2;
#pragma unroll
    for (int mi = 0; mi < 4; mi++) {
        size_t row0 = (size_t)(mBase + wmBase + mi * 16 + lr);
#pragma unroll
        for (int ni = 0; ni < 4; ni++) {
            int col = nBase + wnBase + ni * 8 + lc;
            float bb0 = bias[col], bb1 = bias[col + 1];
            float v[4] = {acc[mi][ni][0] + bb0, acc[mi][ni][1] + bb1,
                          acc[mi][ni][2] + bb0, acc[mi][ni][3] + bb1};
#pragma unroll
            for (int q = 0; q < 4; q++) {
                if (EPI == 1) v[q] = fmaxf(v[q], 0.f) + log1pf(expf(-fabsf(v[q])));
                else if (EPI == 2) v[q] = sigmoidf_(v[q]);
            }
            size_t i0 = row0 * Ntot + col;
            size_t i1 = (row0 + 8) * Ntot + col;
            *(float2*)(C + i0) = make_float2(v[0], v[1]);
            *(float2*)(C + i1) = make_float2(v[2], v[3]);
            if (bout) {
                __nv_bfloat16 h0 = __float2bfloat16(v[0]), h1 = __float2bfloat16(v[1]);
                __nv_bfloat16 h2 = __float2bfloat16(v[2]), h3 = __float2bfloat16(v[3]);
                Ch[i0] = h0; Ch[i0 + 1] = h1; Ch[i1] = h2; Ch[i1 + 1] = h3;
                Cl[i0]     = __float2bfloat16(v[0] - __bfloat162float(h0));
                Cl[i0 + 1] = __float2bfloat16(v[1] - __bfloat162float(h1));
                Cl[i1]     = __float2bfloat16(v[2] - __bfloat162float(h2));
                Cl[i1 + 1] = __float2bfloat16(v[3] - __bfloat162float(h3));
            }
        }
    }
}

// ---------------- MoE gather-GEMM (unchanged, verified) ----------------
constexpr int A_STR = 40;
constexpr int B_STR = 136;

template <int PHASE>
__global__ __launch_bounds__(256)
void moe_tgemm_kernel(const float* __restrict__ Wall, const float* __restrict__ ball) {
    constexpr int K = (PHASE == 1) ? 1024 : 4096;
    constexpr int N = (PHASE == 1) ? 4096 : 1024;
    const int e = blockIdx.z;
    const int mc = g_cnt[e];
    const int m0 = blockIdx.x * 128;
    if (m0 >= mc) return;
    const float* Asrc = (PHASE == 1) ? g_h : g_e1;
    float* Cd = (PHASE == 1) ? g_e1 : g_e2;
    const float* W = Wall + (size_t)e * K * N;
    const float* bias = ball + (size_t)e * N;

    __shared__ int rows[128];
    __shared__ __nv_bfloat16 sAh[128][A_STR];
    __shared__ __nv_bfloat16 sAl[128][A_STR];
    __shared__ __nv_bfloat16 sBh[32][B_STR];
    __shared__ __nv_bfloat16 sBl[32][B_STR];

    const int tid = threadIdx.x;
    const int warp = tid >> 5, lane = tid & 31;
    const int wm = warp & 1, wn = warp >> 1;
    const int nBase = blockIdx.y * 128;
    const int wmBase = wm * 64, wnBase = wn * 32;

    if (tid < 128) {
        int m = m0 + tid;
        rows[tid] = (m < mc) ? g_list[e * 2048 + m] : -1;
    }
    __syncthreads();

    const int arow = tid >> 1, acb = (tid & 1) * 16;
    const int brow = tid >> 3, bcb = (tid & 7) * 16;
    const int arid = rows[arow];
    const size_t srow = (PHASE == 1) ? (size_t)(arid >> 1) : (size_t)arid;

    const int lrow = lane & 15;
    const int lcol = (lane >> 4) << 3;
    const uint32_t aBaseH = smem_u32(&sAh[wmBase + lrow][lcol]);
    const uint32_t aBaseL = smem_u32(&sAl[wmBase + lrow][lcol]);
    const uint32_t bBaseH = smem_u32(&sBh[lrow][wnBase + lcol]);
    const uint32_t bBaseL = smem_u32(&sBl[lrow][wnBase + lcol]);

    float acc[4][4][4] = {};

    for (int k0 = 0; k0 < K; k0 += 32) {
        {
            float av[16];
            if (arid >= 0) {
                const float* ap = Asrc + srow * K + k0 + acb;
                *(float4*)&av[0]  = *(const float4*)(ap);
                *(float4*)&av[4]  = *(const float4*)(ap + 4);
                *(float4*)&av[8]  = *(const float4*)(ap + 8);
                *(float4*)&av[12] = *(const float4*)(ap + 12);
            } else {
#pragma unroll
                for (int i = 0; i < 16; i++) av[i] = 0.f;
            }
            uint32_t hi[8], lo[8];
            cvt_split16(av, hi, lo);
            *(uint4*)&sAh[arow][acb]     = *(uint4*)&hi[0];
            *(uint4*)&sAh[arow][acb + 8] = *(uint4*)&hi[4];
            *(uint4*)&sAl[arow][acb]     = *(uint4*)&lo[0];
            *(uint4*)&sAl[arow][acb + 8] = *(uint4*)&lo[4];
        }
        {
            const float* bp = W + (size_t)(k0 + brow) * N + nBase + bcb;
            float bv[16];
            *(float4*)&bv[0]  = *(const float4*)(bp);
            *(float4*)&bv[4]  = *(const float4*)(bp + 4);
            *(float4*)&bv[8]  = *(const float4*)(bp + 8);
            *(float4*)&bv[12] = *(const float4*)(bp + 12);
            uint32_t hi[8], lo[8];
            cvt_split16(bv, hi, lo);
            *(uint4*)&sBh[brow][bcb]     = *(uint4*)&hi[0];
            *(uint4*)&sBh[brow][bcb + 8] = *(uint4*)&hi[4];
            *(uint4*)&sBl[brow][bcb]     = *(uint4*)&lo[0];
            *(uint4*)&sBl[brow][bcb + 8] = *(uint4*)&lo[4];
        }
        __syncthreads();

#pragma unroll
        for (int chunk = 0; chunk < 2; chunk++) {
            uint32_t Ah[4][4], Al[4][4], Bh[4][2], Bl[4][2];
#pragma unroll
            for (int mi = 0; mi < 4; mi++) {
                ldsm_x4(Ah[mi][0], Ah[mi][1], Ah[mi][2], Ah[mi][3],
                        aBaseH + mi * (16 * A_STR * 2) + chunk * 32);
                ldsm_x4(Al[mi][0], Al[mi][1], Al[mi][2], Al[mi][3],
                        aBaseL + mi * (16 * A_STR * 2) + chunk * 32);
            }
#pragma unroll
            for (int g = 0; g < 2; g++) {
                uint32_t r0, r1, r2, r3;
                ldsm_x4_t(r0, r1, r2, r3, bBaseH + chunk * (16 * B_STR * 2) + g * 32);
                Bh[2 * g][0] = r0; Bh[2 * g][1] = r1; Bh[2 * g + 1][0] = r2; Bh[2 * g + 1][1] = r3;
                ldsm_x4_t(r0, r1, r2, r3, bBaseL + chunk * (16 * B_STR * 2) + g * 32);
                Bl[2 * g][0] = r0; Bl[2 * g][1] = r1; Bl[2 * g + 1][0] = r2; Bl[2 * g + 1][1] = r3;
            }
#pragma unroll
            for (int mi = 0; mi < 4; mi++)
#pragma unroll
                for (int ni = 0; ni < 4; ni++) {
                    mma_bf16(acc[mi][ni], Ah[mi], Bh[ni]);
                    mma_bf16(acc[mi][ni], Ah[mi], Bl[ni]);
                    mma_bf16(acc[mi][ni], Al[mi], Bh[ni]);
                }
        }
        __syncthreads();
    }

    const int lr = lane >> 2, lc = (lane & 3) * 2;
#pragma unroll
    for (int mi = 0; mi < 4; mi++) {
        int a0 = rows[wmBase + mi * 16 + lr];
        int a1 = rows[wmBase + mi * 16 + lr + 8];
        float w0 = (PHASE == 2 && a0 >= 0) ? g_w[a0] : 1.f;
        float w1 = (PHASE == 2 && a1 >= 0) ? g_w[a1] : 1.f;
#pragma unroll
        for (int ni = 0; ni < 4; ni++) {
            int col = nBase + wnBase + ni * 8 + lc;
            float b0 = bias[col], b1 = bias[col + 1];
            float v00 = acc[mi][ni][0] + b0, v01 = acc[mi][ni][1] + b1;
            float v10 = acc[mi][ni][2] + b0, v11 = acc[mi][ni][3] + b1;
            if (PHASE == 1) {
                v00 *= sigmoidf_(v00); v01 *= sigmoidf_(v01);
                v10 *= sigmoidf_(v10); v11 *= sigmoidf_(v11);
            } else {
                v00 *= w0; v01 *= w0; v10 *= w1; v11 *= w1;
            }
            if (a0 >= 0) *(float2*)(Cd + (size_t)a0 * N + col) = make_float2(v00, v01);
            if (a1 >= 0) *(float2*)(Cd + (size_t)a1 * N + col) = make_float2(v10, v11);
        }
    }
}

// ---------------- x -> bf16 hi/lo ----------------
__global__ void convx_kernel(const float* __restrict__ x) {
    int i = (blockIdx.x * 256 + threadIdx.x) * 4;
    float4 v = *(const float4*)(x + i);
    float a[4] = {v.x, v.y, v.z, v.w};
#pragma unroll
    for (int j = 0; j < 4; j++) {
        __nv_bfloat16 h = __float2bfloat16(a[j]);
        g_xh[i + j] = h;
        g_xl[i + j] = __float2bfloat16(a[j] - __bfloat162float(h));
    }
}

// ---------------- rotary ----------------
__global__ void rotary_kernel(const float* __restrict__ sinp, const float* __restrict__ cosp) {
    int r = blockIdx.x;
    int t = r & (T_ - 1);
    const float* pr = g_P + (size_t)r * 2048;
    float* xr = g_XR + (size_t)r * 1024;
    for (int i = threadIdx.x; i < 512; i += 256) {
        float c = cosp[t * 512 + i], s = sinp[t * 512 + i];
        float a0 = pr[2 * i], a1 = pr[2 * i + 1];
        xr[2 * i]     = a0 * c - a1 * s;
        xr[2 * i + 1] = a0 * s + a1 * c;
    }
}

// ---------------- dwconv + gate + RMS -> glcm ----------------
__global__ void glcm_kernel(const float* __restrict__ Wdw, const float* __restrict__ bdw,
                            const float* __restrict__ gg) {
    int r = blockIdx.x;
    int b = r >> 9, t = r & 511;
    float vals[4];
    float ss = 0.f;
#pragma unroll
    for (int j = 0; j < 4; j++) {
        int d = threadIdx.x + j * 256;
        float conv = bdw[d];
#pragma unroll
        for (int k = 0; k < 7; k++) {
            int tt = t + k - 3;
            if (tt >= 0 && tt < T_)
                conv += g_XR[(size_t)(b * T_ + tt) * 1024 + d] * Wdw[k * 1024 + d];
        }
        float xb = g_P[(size_t)r * 2048 + 1024 + d];
        float v = conv * sigmoidf_(conv) * sigmoidf_(xb);
        vals[j] = v;
        ss += v * v;
    }
    ss = block_sum256(ss);
    float inv = 1.f / sqrtf(ss * (1.f / 1024.f) + EPS_);
#pragma unroll
    for (int j = 0; j < 4; j++) {
        int d = threadIdx.x + j * 256;
        g_glcm[(size_t)r * 1024 + d] = gg[d] * vals[j] * inv;
    }
}

// ---------------- sequential S6 scan (also emits y bf16 hi/lo) ----------------
__global__ void scan_kernel(const float* __restrict__ Alog) {
    int gw = (blockIdx.x * blockDim.x + threadIdx.x) >> 5;
    int lane = threadIdx.x & 31;
    int b = gw >> 9;
    int spair = gw & 511;
    int half = lane >> 4, n = lane & 15;
    int s = spair * 2 + half;
    float A = -expf(Alog[s * 16 + n]);
    float h = 0.f;
    const int base_r = b * T_;
    for (int t = 0; t < T_; t++) {
        int r = base_r + t;
        float d  = g_delta[(size_t)r * 1024 + s];
        float u  = g_XI[(size_t)r * 2048 + s];
        float Bv = g_Bmat[(size_t)r * 16384 + s * 16 + n];
        float Cv = g_Cmat[(size_t)r * 16384 + s * 16 + n];
        h = expf(d * A) * h + (d * u) * Bv;
        float p = h * Cv;
        p += __shfl_xor_sync(0xffffffffu, p, 1);
        p += __shfl_xor_sync(0xffffffffu, p, 2);
        p += __shfl_xor_sync(0xffffffffu, p, 4);
        p += __shfl_xor_sync(0xffffffffu, p, 8);
        if (n == 0) {
            size_t idx = (size_t)r * 1024 + s;
            g_y[idx] = p;
            __nv_bfloat16 hh = __float2bfloat16(p);
            g_yh[idx] = hh;
            g_yl[idx] = __float2bfloat16(p - __bfloat162float(hh));
        }
    }
}

// ---------------- RMS ----------------
__global__ void rms_kernel(const float* __restrict__ gg) {
    int r = blockIdx.x;
    const float* xin = g_yo + (size_t)r * 1024;
    float vals[4];
    float ss = 0.f;
#pragma unroll
    for (int j = 0; j < 4; j++) {
        int d = threadIdx.x + j * 256;
        float v = xin[d];
        vals[j] = v;
        ss += v * v;
    }
    ss = block_sum256(ss);
    float inv = 1.f / sqrtf(ss * (1.f / 1024.f) + EPS_);
#pragma unroll
    for (int j = 0; j < 4; j++) {
        int d = threadIdx.x + j * 256;
        g_s6[(size_t)r * 1024 + d] = gg[d] * vals[j] * inv;
    }
}

// ---------------- combine ----------------
__global__ void combine_kernel(const float* __restrict__ x, const float* __restrict__ gfg) {
    int r = blockIdx.x;
    float vals[4];
    float ss = 0.f;
#pragma unroll
    for (int j = 0; j < 4; j++) {
        int d = threadIdx.x + j * 256;
        size_t idx = (size_t)r * 1024 + d;
        float v = g_g1[idx] * g_s6[idx] + g_g2[idx] * g_glcm[idx];
        vals[j] = v;
        ss += v * v;
    }
    ss = block_sum256(ss);
    float inv = 1.f / sqrtf(ss * (1.f / 1024.f) + EPS_);
#pragma unroll
    for (int j = 0; j < 4; j++) {
        int d = threadIdx.x + j * 256;
        size_t idx = (size_t)r * 1024 + d;
        g_h[idx] = x[idx] + gfg[d] * vals[j] * inv;
    }
}

// ---------------- MoE routing ----------------
__global__ void zero_cnt_kernel() {
    if (threadIdx.x < E_) g_cnt[threadIdx.x] = 0;
}

__global__ void route_kernel(const float* __restrict__ Wg) {
    int warp = threadIdx.x >> 5, lane = threadIdx.x & 31;
    int token = blockIdx.x * 8 + warp;
    float acc[16];
#pragma unroll
    for (int e = 0; e < 16; e++) acc[e] = 0.f;
    const float* hrow = g_h + (size_t)token * 1024;
    for (int d = lane; d < 1024; d += 32) {
        float xv = hrow[d];
#pragma unroll
        for (int e = 0; e < 16; e++) acc[e] += xv * Wg[d * 16 + e];
    }
#pragma unroll
    for (int e = 0; e < 16; e++) {
#pragma unroll
        for (int o = 16; o; o >>= 1) acc[e] += __shfl_xor_sync(0xffffffffu, acc[e], o);
    }
    if (lane == 0) {
        float v0 = -1e30f; int i0 = 0;
#pragma unroll
        for (int e = 0; e < 16; e++) if (acc[e] > v0) { v0 = acc[e]; i0 = e; }
        float v1 = -1e30f; int i1 = 0;
#pragma unroll
        for (int e = 0; e < 16; e++) if (e != i0 && acc[e] > v1) { v1 = acc[e]; i1 = e; }
        float w0 = 1.f / (1.f + expf(v1 - v0));
        g_w[token * 2]     = w0;
        g_w[token * 2 + 1] = 1.f - w0;
        int p0 = atomicAdd(&g_cnt[i0], 1);
        g_list[i0 * 2048 + p0] = token * 2;
        int p1 = atomicAdd(&g_cnt[i1], 1);
        g_list[i1 * 2048 + p1] = token * 2 + 1;
    }
}

// ---------------- final ----------------
__global__ void final_kernel(float* __restrict__ out) {
    int idx = blockIdx.x * 256 + threadIdx.x;
    int r = idx >> 10, d = idx & 1023;
    out[idx] = g_h[idx] + g_e2[(size_t)r * 2048 + d] + g_e2[(size_t)r * 2048 + 1024 + d];
}

// ---------------- launch ----------------
extern "C" void kernel_launch(void* const* d_in, const int* /*in_sizes*/, int /*n_in*/,
                              void* d_out, int /*out_size*/) {
    const float* x    = (const float*)d_in[0];
    const float* sinp = (const float*)d_in[1];
    const float* cosp = (const float*)d_in[2];
    const float* Wp   = (const float*)d_in[3];
    const float* bp   = (const float*)d_in[4];
    const float* Wdw  = (const float*)d_in[5];
    const float* bdw  = (const float*)d_in[6];
    const float* glg  = (const float*)d_in[7];
    const float* Win  = (const float*)d_in[8];
    const float* bin  = (const float*)d_in[9];
    const float* Wd   = (const float*)d_in[10];
    const float* bd   = (const float*)d_in[11];
    const float* WB   = (const float*)d_in[12];
    const float* bB   = (const float*)d_in[13];
    const float* WC   = (const float*)d_in[14];
    const float* bC   = (const float*)d_in[15];
    const float* Alog = (const float*)d_in[16];
    const float* Wout = (const float*)d_in[17];
    const float* bout = (const float*)d_in[18];
    const float* s6g  = (const float*)d_in[19];
    const float* gfW1 = (const float*)d_in[20];
    const float* gfb1 = (const float*)d_in[21];
    const float* gfW2 = (const float*)d_in[22];
    const float* gfb2 = (const float*)d_in[23];
    const float* gfg  = (const float*)d_in[24];
    const float* Wg   = (const float*)d_in[25];
    const float* mW1  = (const float*)d_in[26];
    const float* mb1  = (const float*)d_in[27];
    const float* mW2  = (const float*)d_in[28];
    const float* mb2  = (const float*)d_in[29];
    float* out = (float*)d_out;

    cudaFuncSetAttribute(wgemm<0>, cudaFuncAttributeMaxDynamicSharedMemorySize, DSMEM);
    cudaFuncSetAttribute(wgemm<1>, cudaFuncAttributeMaxDynamicSharedMemorySize, DSMEM);
    cudaFuncSetAttribute(wgemm<2>, cudaFuncAttributeMaxDynamicSharedMemorySize, DSMEM);

    float *pP, *pXI, *pDelta, *pB, *pC, *pYO, *pG1, *pG2;
    cudaGetSymbolAddress((void**)&pP,     g_P);
    cudaGetSymbolAddress((void**)&pXI,    g_XI);
    cudaGetSymbolAddress((void**)&pDelta, g_delta);
    cudaGetSymbolAddress((void**)&pB,     g_Bmat);
    cudaGetSymbolAddress((void**)&pC,     g_Cmat);
    cudaGetSymbolAddress((void**)&pYO,    g_yo);
    cudaGetSymbolAddress((void**)&pG1,    g_g1);
    cudaGetSymbolAddress((void**)&pG2,    g_g2);

    __nv_bfloat16 *xh, *xl, *XIh, *XIl, *yh, *yl;
    cudaGetSymbolAddress((void**)&xh,  g_xh);  cudaGetSymbolAddress((void**)&xl,  g_xl);
    cudaGetSymbolAddress((void**)&XIh, g_XIh); cudaGetSymbolAddress((void**)&XIl, g_XIl);
    cudaGetSymbolAddress((void**)&yh,  g_yh);  cudaGetSymbolAddress((void**)&yl,  g_yl);

    // 0) x -> bf16 hi/lo mirror (reused by 4 GEMMs)
    convx_kernel<<<1024, 256>>>(x);

    // 1+2) P = x@Wp+bp (z=0), XI = x@Win+bin (z=1, emits bf16 mirrors)
    wgemm<0><<<dim3(8, 16, 2), 256, DSMEM>>>(xh, xl, Wp, Win, bp, bin, pP, pXI, XIh, XIl, 2048, 1024);
    // 3) rotary + glcm
    rotary_kernel<<<BT, 256>>>(sinp, cosp);
    glcm_kernel<<<BT, 256>>>(Wdw, bdw, glg);
    // 5) delta = softplus(XI @ Wd + bd)
    wgemm<1><<<dim3(8, 8, 1), 256, DSMEM>>>(XIh, XIl, Wd, Wd, bd, bd, pDelta, pDelta, nullptr, nullptr, 1024, 2048);
    // 6/7) B, C projections (weights converted in-kernel, f32 read once)
    wgemm<0><<<dim3(8, 128, 1), 256, DSMEM>>>(XIh, XIl, WB, WB, bB, bB, pB, pB, nullptr, nullptr, 16384, 2048);
    wgemm<0><<<dim3(8, 128, 1), 256, DSMEM>>>(XIh, XIl, WC, WC, bC, bC, pC, pC, nullptr, nullptr, 16384, 2048);
    // 8) scan
    scan_kernel<<<128, 256>>>(Alog);
    // 9) yo = y @ Wout + bout ; rms
    wgemm<0><<<dim3(8, 8, 1), 256, DSMEM>>>(yh, yl, Wout, Wout, bout, bout, pYO, pYO, nullptr, nullptr, 1024, 1024);
    rms_kernel<<<BT, 256>>>(s6g);
    // 10) gates g1 (z=0), g2 (z=1)
    wgemm<2><<<dim3(8, 8, 2), 256, DSMEM>>>(xh, xl, gfW1, gfW2, gfb1, gfb2, pG1, pG2, nullptr, nullptr, 1024, 1024);
    // 11) combine
    combine_kernel<<<BT, 256>>>(x, gfg);
    // 12) routing
    zero_cnt_kernel<<<1, 32>>>();
    route_kernel<<<128, 256>>>(Wg);
    // 13/14) expert FFN
    moe_tgemm_kernel<1><<<dim3(16, 32, 16), 256>>>(mW1, mb1);
    moe_tgemm_kernel<2><<<dim3(16, 8, 16), 256>>>(mW2, mb2);
    // 15) final
    final_kernel<<<4096, 256>>>(out);
}

// round 12
// speedup vs baseline: 3.6612x; 1.0635x over previous
#include <cuda_runtime.h>
#include <cuda_bf16.h>
#include <cuda_fp16.h>
#include <math.h>
#include <stdint.h>

// ---------------- constants ----------------
constexpr int E_  = 16;
constexpr int T_  = 512;
constexpr int BT  = 1024;   // B*T
constexpr float EPS_ = 1e-8f;

// ---------------- f32 scratch ----------------
__device__ float g_P    [BT * 2048];
__device__ float g_XI   [BT * 2048];
__device__ float g_XR   [BT * 1024];
__device__ float g_glcm [BT * 1024];
__device__ float g_delta[BT * 1024];
__device__ float g_Bmat [BT * 16384];
__device__ float g_Cmat [BT * 16384];
__device__ float g_y    [BT * 1024];
__device__ float g_yo   [BT * 1024];
__device__ float g_s6   [BT * 1024];
__device__ float g_g1   [BT * 1024];
__device__ float g_g2   [BT * 1024];
__device__ float g_h    [BT * 1024];
__device__ float g_e2   [2 * BT * 1024];
__device__ int   g_cnt  [E_];
__device__ int   g_list [E_ * 2048];
__device__ float g_w    [2 * BT];

// ---------------- fp16 MoE intermediate ----------------
__device__ __half g_e1h [2 * BT * 4096];

// ---------------- bf16 hi/lo activation mirrors (dense path) ----------------
__device__ __nv_bfloat16 g_xh [BT * 1024], g_xl [BT * 1024];
__device__ __nv_bfloat16 g_XIh[BT * 2048], g_XIl[BT * 2048];
__device__ __nv_bfloat16 g_yh [BT * 1024], g_yl [BT * 1024];

// ---------------- helpers ----------------
__device__ __forceinline__ float sigmoidf_(float x) { return 1.f / (1.f + expf(-x)); }

__device__ __forceinline__ float block_sum256(float v) {
    __shared__ float sh[8];
    int lane = threadIdx.x & 31, w = threadIdx.x >> 5;
#pragma unroll
    for (int o = 16; o; o >>= 1) v += __shfl_xor_sync(0xffffffffu, v, o);
    if (lane == 0) sh[w] = v;
    __syncthreads();
    float s = 0.f;
#pragma unroll
    for (int i = 0; i < 8; i++) s += sh[i];
    return s;
}

__device__ __forceinline__ uint32_t smem_u32(const void* p) {
    return (uint32_t)__cvta_generic_to_shared(p);
}

__device__ __forceinline__ void ldsm_x4(uint32_t& r0, uint32_t& r1, uint32_t& r2, uint32_t& r3, uint32_t addr) {
    asm volatile("ldmatrix.sync.aligned.m8n8.x4.shared.b16 {%0,%1,%2,%3}, [%4];"
        : "=r"(r0), "=r"(r1), "=r"(r2), "=r"(r3) : "r"(addr));
}
__device__ __forceinline__ void ldsm_x4_t(uint32_t& r0, uint32_t& r1, uint32_t& r2, uint32_t& r3, uint32_t addr) {
    asm volatile("ldmatrix.sync.aligned.m8n8.x4.trans.shared.b16 {%0,%1,%2,%3}, [%4];"
        : "=r"(r0), "=r"(r1), "=r"(r2), "=r"(r3) : "r"(addr));
}
__device__ __forceinline__ void mma_bf16(float* c, const uint32_t* a, const uint32_t* b) {
    asm volatile("mma.sync.aligned.m16n8k16.row.col.f32.bf16.bf16.f32 "
        "{%0,%1,%2,%3}, {%4,%5,%6,%7}, {%8,%9}, {%0,%1,%2,%3};"
        : "+f"(c[0]), "+f"(c[1]), "+f"(c[2]), "+f"(c[3])
        : "r"(a[0]), "r"(a[1]), "r"(a[2]), "r"(a[3]), "r"(b[0]), "r"(b[1]));
}
__device__ __forceinline__ void mma_f16(float* c, const uint32_t* a, const uint32_t* b) {
    asm volatile("mma.sync.aligned.m16n8k16.row.col.f32.f16.f16.f32 "
        "{%0,%1,%2,%3}, {%4,%5,%6,%7}, {%8,%9}, {%0,%1,%2,%3};"
        : "+f"(c[0]), "+f"(c[1]), "+f"(c[2]), "+f"(c[3])
        : "r"(a[0]), "r"(a[1]), "r"(a[2]), "r"(a[3]), "r"(b[0]), "r"(b[1]));
}
__device__ __forceinline__ void cvt_split16(const float* v, uint32_t* hi, uint32_t* lo) {
#pragma unroll
    for (int i = 0; i < 8; i++) {
        float x0 = v[2 * i], x1 = v[2 * i + 1];
        __nv_bfloat16 h0 = __float2bfloat16(x0), h1 = __float2bfloat16(x1);
        float r0 = x0 - __bfloat162float(h0), r1 = x1 - __bfloat162float(h1);
        __nv_bfloat16 l0 = __float2bfloat16(r0), l1 = __float2bfloat16(r1);
        hi[i] = ((uint32_t)__bfloat16_as_ushort(h1) << 16) | __bfloat16_as_ushort(h0);
        lo[i] = ((uint32_t)__bfloat16_as_ushort(l1) << 16) | __bfloat16_as_ushort(l0);
    }
}
__device__ __forceinline__ void cvt_h16(const float* v, uint32_t* h) {
#pragma unroll
    for (int i = 0; i < 8; i++) {
        __half2 p = __floats2half2_rn(v[2 * i], v[2 * i + 1]);
        h[i] = *(uint32_t*)&p;
    }
}

__device__ __forceinline__ void cp16(uint32_t dst, const void* src) {
    asm volatile("cp.async.cg.shared.global [%0], [%1], 16;" :: "r"(dst), "l"(src));
}
#define CP_COMMIT() asm volatile("cp.async.commit_group;" ::: "memory")
#define CP_WAIT1()  asm volatile("cp.async.wait_group 1;" ::: "memory")

// ============================================================================
// Dense GEMM (3-pass bf16 split; unchanged from R10 baseline)
// ============================================================================
constexpr int AP = 10240;            // bytes per A plane (128*40*2)
constexpr int BP = 8704;             // bytes per B plane (32*136*2)
constexpr int STG = 2 * AP + 2 * BP; // 37888 per stage
constexpr int DSMEM = 2 * STG;       // 75776

template <int EPI>   // EPI: 0 none, 1 softplus, 2 sigmoid
__global__ __launch_bounds__(256)
void wgemm(const __nv_bfloat16* __restrict__ Ah, const __nv_bfloat16* __restrict__ Al,
           const float* __restrict__ W0, const float* __restrict__ W1,
           const float* __restrict__ b0, const float* __restrict__ b1,
           float* __restrict__ C0, float* __restrict__ C1,
           __nv_bfloat16* __restrict__ Ch, __nv_bfloat16* __restrict__ Cl,
           int Ntot, int K) {
    extern __shared__ char smem[];
    const uint32_t sb = smem_u32(smem);

    const int z = blockIdx.z;
    const float* __restrict__ W    = z ? W1 : W0;
    const float* __restrict__ bias = z ? b1 : b0;
    float* __restrict__ C          = z ? C1 : C0;
    const bool bout = (Ch != nullptr) && (z == 1);

    const int tid = threadIdx.x;
    const int warp = tid >> 5, lane = tid & 31;
    const int wm = warp & 1, wn = warp >> 1;
    const int mBase = blockIdx.x * 128, nBase = blockIdx.y * 128;
    const int wmBase = wm * 64, wnBase = wn * 32;

    const int S = K >> 5;

    auto load_A = [&](int s, int b) {
        const int k0 = s << 5;
        const uint32_t base = sb + b * STG;
#pragma unroll
        for (int i = 0; i < 2; i++) {
            int c = i * 256 + tid;
            int r = c >> 2, c4 = c & 3;
            uint32_t dst = base + (uint32_t)(r * 80 + c4 * 16);
            cp16(dst,      Ah + (size_t)(mBase + r) * K + k0 + c4 * 8);
            cp16(dst + AP, Al + (size_t)(mBase + r) * K + k0 + c4 * 8);
        }
    };

    const int wr = tid >> 3, wc = (tid & 7) * 16;
    float wreg[16];
    auto ldg_W = [&](int s) {
        const float* src = W + (size_t)((s << 5) + wr) * Ntot + nBase + wc;
        *(float4*)&wreg[0]  = *(const float4*)(src);
        *(float4*)&wreg[4]  = *(const float4*)(src + 4);
        *(float4*)&wreg[8]  = *(const float4*)(src + 8);
        *(float4*)&wreg[12] = *(const float4*)(src + 12);
    };
    auto sts_W = [&](int b) {
        uint32_t hi[8], lo[8];
        cvt_split16(wreg, hi, lo);
        const uint32_t off = b * STG + 2 * AP + (uint32_t)(wr * 272 + wc * 2);
        *(uint4*)(smem + off)           = *(uint4*)&hi[0];
        *(uint4*)(smem + off + 16)      = *(uint4*)&hi[4];
        *(uint4*)(smem + off + BP)      = *(uint4*)&lo[0];
        *(uint4*)(smem + off + BP + 16) = *(uint4*)&lo[4];
    };

    float acc[4][4][4] = {};

    const int lrow = lane & 15;
    const int lcolB = ((lane >> 4) << 3) * 2;

    ldg_W(0);
    load_A(0, 0); CP_COMMIT();
    load_A(1, 1); CP_COMMIT();

    for (int s = 0; s < S; s++) {
        const int b = s & 1;
        sts_W(b);
        if (s + 1 < S) ldg_W(s + 1);
        CP_WAIT1();
        __syncthreads();

        const uint32_t base = sb + b * STG;
        const uint32_t aH = base + (uint32_t)((wmBase + lrow) * 80) + lcolB;
        const uint32_t aL = aH + AP;
        const uint32_t bH = base + 2 * AP + (uint32_t)(lrow * 272) + (uint32_t)(wnBase * 2) + lcolB;
        const uint32_t bL = bH + BP;

#pragma unroll
        for (int chunk = 0; chunk < 2; chunk++) {
            uint32_t Afh[4][4], Afl[4][4], Bfh[4][2], Bfl[4][2];
#pragma unroll
            for (int mi = 0; mi < 4; mi++) {
                ldsm_x4(Afh[mi][0], Afh[mi][1], Afh[mi][2], Afh[mi][3],
                        aH + mi * (16 * 80) + chunk * 32);
                ldsm_x4(Afl[mi][0], Afl[mi][1], Afl[mi][2], Afl[mi][3],
                        aL + mi * (16 * 80) + chunk * 32);
            }
#pragma unroll
            for (int g = 0; g < 2; g++) {
                uint32_t r0, r1, r2, r3;
                ldsm_x4_t(r0, r1, r2, r3, bH + chunk * (16 * 272) + g * 32);
                Bfh[2 * g][0] = r0; Bfh[2 * g][1] = r1; Bfh[2 * g + 1][0] = r2; Bfh[2 * g + 1][1] = r3;
                ldsm_x4_t(r0, r1, r2, r3, bL + chunk * (16 * 272) + g * 32);
                Bfl[2 * g][0] = r0; Bfl[2 * g][1] = r1; Bfl[2 * g + 1][0] = r2; Bfl[2 * g + 1][1] = r3;
            }
#pragma unroll
            for (int mi = 0; mi < 4; mi++)
#pragma unroll
                for (int ni = 0; ni < 4; ni++) {
                    mma_bf16(acc[mi][ni], Afh[mi], Bfh[ni]);
                    mma_bf16(acc[mi][ni], Afh[mi], Bfl[ni]);
                    mma_bf16(acc[mi][ni], Afl[mi], Bfh[ni]);
                }
        }
        __syncthreads();
        if (s + 2 < S) load_A(s + 2, b);
        CP_COMMIT();
    }

    const int lr = lane >> 2, lc = (lane & 3) * 2;
#pragma unroll
    for (int mi = 0; mi < 4; mi++) {
        size_t row0 = (size_t)(mBase + wmBase + mi * 16 + lr);
#pragma unroll
        for (int ni = 0; ni < 4; ni++) {
            int col = nBase + wnBase + ni * 8 + lc;
            float bb0 = bias[col], bb1 = bias[col + 1];
            float v[4] = {acc[mi][ni][0] + bb0, acc[mi][ni][1] + bb1,
                          acc[mi][ni][2] + bb0, acc[mi][ni][3] + bb1};
#pragma unroll
            for (int q = 0; q < 4; q++) {
                if (EPI == 1) v[q] = fmaxf(v[q], 0.f) + log1pf(expf(-fabsf(v[q])));
                else if (EPI == 2) v[q] = sigmoidf_(v[q]);
            }
            size_t i0 = row0 * Ntot + col;
            size_t i1 = (row0 + 8) * Ntot + col;
            *(float2*)(C + i0) = make_float2(v[0], v[1]);
            *(float2*)(C + i1) = make_float2(v[2], v[3]);
            if (bout) {
                __nv_bfloat16 h0 = __float2bfloat16(v[0]), h1 = __float2bfloat16(v[1]);
                __nv_bfloat16 h2 = __float2bfloat16(v[2]), h3 = __float2bfloat16(v[3]);
                Ch[i0] = h0; Ch[i0 + 1] = h1; Ch[i1] = h2; Ch[i1 + 1] = h3;
                Cl[i0]     = __float2bfloat16(v[0] - __bfloat162float(h0));
                Cl[i0 + 1] = __float2bfloat16(v[1] - __bfloat162float(h1));
                Cl[i1]     = __float2bfloat16(v[2] - __bfloat162float(h2));
                Cl[i1 + 1] = __float2bfloat16(v[3] - __bfloat162float(h3));
            }
        }
    }
}

// ============================================================================
// MoE gather-GEMM, SINGLE-PASS fp16 (routing-independent path; err ~3e-4 on e2)
// PHASE 1: e1h[a] = half(silu(h[a>>1] @ W1[e] + b1[e])),  K=1024, N=4096
// PHASE 2: e2[a]  = (e1h[a] @ W2[e] + b2[e]) * w[a],      K=4096, N=1024
// ============================================================================
constexpr int MA_STR = 40;
constexpr int MB_STR = 136;

template <int PHASE>
__global__ __launch_bounds__(256)
void moe_fp16_kernel(const float* __restrict__ Wall, const float* __restrict__ ball) {
    constexpr int K = (PHASE == 1) ? 1024 : 4096;
    constexpr int N = (PHASE == 1) ? 4096 : 1024;
    const int e = blockIdx.z;
    const int mc = g_cnt[e];
    const int m0 = blockIdx.x * 128;
    if (m0 >= mc) return;
    const float* W = Wall + (size_t)e * K * N;
    const float* bias = ball + (size_t)e * N;

    __shared__ int rows[128];
    __shared__ __half sA[128][MA_STR];
    __shared__ __half sB[32][MB_STR];

    const int tid = threadIdx.x;
    const int warp = tid >> 5, lane = tid & 31;
    const int wm = warp & 1, wn = warp >> 1;
    const int nBase = blockIdx.y * 128;
    const int wmBase = wm * 64, wnBase = wn * 32;

    if (tid < 128) {
        int m = m0 + tid;
        rows[tid] = (m < mc) ? g_list[e * 2048 + m] : -1;
    }
    __syncthreads();

    const int arow = tid >> 1, acb = (tid & 1) * 16;
    const int brow = tid >> 3, bcb = (tid & 7) * 16;
    const int arid = rows[arow];

    const int lrow = lane & 15;
    const int lcol = (lane >> 4) << 3;
    const uint32_t aBase = smem_u32(&sA[wmBase + lrow][lcol]);
    const uint32_t bBase = smem_u32(&sB[lrow][wnBase + lcol]);

    float acc[4][4][4] = {};

    for (int k0 = 0; k0 < K; k0 += 32) {
        // stage A (16 halfs per thread)
        if (PHASE == 1) {
            float av[16];
            if (arid >= 0) {
                const float* ap = g_h + (size_t)(arid >> 1) * 1024 + k0 + acb;
                *(float4*)&av[0]  = *(const float4*)(ap);
                *(float4*)&av[4]  = *(const float4*)(ap + 4);
                *(float4*)&av[8]  = *(const float4*)(ap + 8);
                *(float4*)&av[12] = *(const float4*)(ap + 12);
            } else {
#pragma unroll
                for (int i = 0; i < 16; i++) av[i] = 0.f;
            }
            uint32_t hw[8];
            cvt_h16(av, hw);
            *(uint4*)&sA[arow][acb]     = *(uint4*)&hw[0];
            *(uint4*)&sA[arow][acb + 8] = *(uint4*)&hw[4];
        } else {
            uint4 v0 = make_uint4(0, 0, 0, 0), v1 = make_uint4(0, 0, 0, 0);
            if (arid >= 0) {
                const __half* ap = g_e1h + (size_t)arid * 4096 + k0 + acb;
                v0 = *(const uint4*)(ap);
                v1 = *(const uint4*)(ap + 8);
            }
            *(uint4*)&sA[arow][acb]     = v0;
            *(uint4*)&sA[arow][acb + 8] = v1;
        }
        // stage B (16 f32 -> 16 halfs per thread)
        {
            const float* bp = W + (size_t)(k0 + brow) * N + nBase + bcb;
            float bv[16];
            *(float4*)&bv[0]  = *(const float4*)(bp);
            *(float4*)&bv[4]  = *(const float4*)(bp + 4);
            *(float4*)&bv[8]  = *(const float4*)(bp + 8);
            *(float4*)&bv[12] = *(const float4*)(bp + 12);
            uint32_t hw[8];
            cvt_h16(bv, hw);
            *(uint4*)&sB[brow][bcb]     = *(uint4*)&hw[0];
            *(uint4*)&sB[brow][bcb + 8] = *(uint4*)&hw[4];
        }
        __syncthreads();

#pragma unroll
        for (int chunk = 0; chunk < 2; chunk++) {
            uint32_t Af[4][4], Bf[4][2];
#pragma unroll
            for (int mi = 0; mi < 4; mi++)
                ldsm_x4(Af[mi][0], Af[mi][1], Af[mi][2], Af[mi][3],
                        aBase + mi * (16 * MA_STR * 2) + chunk * 32);
#pragma unroll
            for (int g = 0; g < 2; g++) {
                uint32_t r0, r1, r2, r3;
                ldsm_x4_t(r0, r1, r2, r3, bBase + chunk * (16 * MB_STR * 2) + g * 32);
                Bf[2 * g][0] = r0; Bf[2 * g][1] = r1; Bf[2 * g + 1][0] = r2; Bf[2 * g + 1][1] = r3;
            }
#pragma unroll
            for (int mi = 0; mi < 4; mi++)
#pragma unroll
                for (int ni = 0; ni < 4; ni++)
                    mma_f16(acc[mi][ni], Af[mi], Bf[ni]);
        }
        __syncthreads();
    }

    const int lr = lane >> 2, lc = (lane & 3) * 2;
#pragma unroll
    for (int mi = 0; mi < 4; mi++) {
        int a0 = rows[wmBase + mi * 16 + lr];
        int a1 = rows[wmBase + mi * 16 + lr + 8];
#pragma unroll
        for (int ni = 0; ni < 4; ni++) {
            int col = nBase + wnBase + ni * 8 + lc;
            float b0 = bias[col], b1 = bias[col + 1];
            float v00 = acc[mi][ni][0] + b0, v01 = acc[mi][ni][1] + b1;
            float v10 = acc[mi][ni][2] + b0, v11 = acc[mi][ni][3] + b1;
            if (PHASE == 1) {
                v00 *= sigmoidf_(v00); v01 *= sigmoidf_(v01);
                v10 *= sigmoidf_(v10); v11 *= sigmoidf_(v11);
                if (a0 >= 0) {
                    __half2 p = __floats2half2_rn(v00, v01);
                    *(__half2*)(g_e1h + (size_t)a0 * 4096 + col) = p;
                }
                if (a1 >= 0) {
                    __half2 p = __floats2half2_rn(v10, v11);
                    *(__half2*)(g_e1h + (size_t)a1 * 4096 + col) = p;
                }
            } else {
                float w0 = (a0 >= 0) ? g_w[a0] : 0.f;
                float w1 = (a1 >= 0) ? g_w[a1] : 0.f;
                if (a0 >= 0) *(float2*)(g_e2 + (size_t)a0 * 1024 + col) = make_float2(v00 * w0, v01 * w0);
                if (a1 >= 0) *(float2*)(g_e2 + (size_t)a1 * 1024 + col) = make_float2(v10 * w1, v11 * w1);
            }
        }
    }
}

// ---------------- x -> bf16 hi/lo ----------------
__global__ void convx_kernel(const float* __restrict__ x) {
    int i = (blockIdx.x * 256 + threadIdx.x) * 4;
    float4 v = *(const float4*)(x + i);
    float a[4] = {v.x, v.y, v.z, v.w};
#pragma unroll
    for (int j = 0; j < 4; j++) {
        __nv_bfloat16 h = __float2bfloat16(a[j]);
        g_xh[i + j] = h;
        g_xl[i + j] = __float2bfloat16(a[j] - __bfloat162float(h));
    }
}

// ---------------- rotary ----------------
__global__ void rotary_kernel(const float* __restrict__ sinp, const float* __restrict__ cosp) {
    int r = blockIdx.x;
    int t = r & (T_ - 1);
    const float* pr = g_P + (size_t)r * 2048;
    float* xr = g_XR + (size_t)r * 1024;
    for (int i = threadIdx.x; i < 512; i += 256) {
        float c = cosp[t * 512 + i], s = sinp[t * 512 + i];
        float a0 = pr[2 * i], a1 = pr[2 * i + 1];
        xr[2 * i]     = a0 * c - a1 * s;
        xr[2 * i + 1] = a0 * s + a1 * c;
    }
}

// ---------------- dwconv + gate + RMS -> glcm ----------------
__global__ void glcm_kernel(const float* __restrict__ Wdw, const float* __restrict__ bdw,
                            const float* __restrict__ gg) {
    int r = blockIdx.x;
    int b = r >> 9, t = r & 511;
    float vals[4];
    float ss = 0.f;
#pragma unroll
    for (int j = 0; j < 4; j++) {
        int d = threadIdx.x + j * 256;
        float conv = bdw[d];
#pragma unroll
        for (int k = 0; k < 7; k++) {
            int tt = t + k - 3;
            if (tt >= 0 && tt < T_)
                conv += g_XR[(size_t)(b * T_ + tt) * 1024 + d] * Wdw[k * 1024 + d];
        }
        float xb = g_P[(size_t)r * 2048 + 1024 + d];
        float v = conv * sigmoidf_(conv) * sigmoidf_(xb);
        vals[j] = v;
        ss += v * v;
    }
    ss = block_sum256(ss);
    float inv = 1.f / sqrtf(ss * (1.f / 1024.f) + EPS_);
#pragma unroll
    for (int j = 0; j < 4; j++) {
        int d = threadIdx.x + j * 256;
        g_glcm[(size_t)r * 1024 + d] = gg[d] * vals[j] * inv;
    }
}

// ---------------- sequential S6 scan (also emits y bf16 hi/lo) ----------------
__global__ void scan_kernel(const float* __restrict__ Alog) {
    int gw = (blockIdx.x * blockDim.x + threadIdx.x) >> 5;
    int lane = threadIdx.x & 31;
    int b = gw >> 9;
    int spair = gw & 511;
    int half = lane >> 4, n = lane & 15;
    int s = spair * 2 + half;
    float A = -expf(Alog[s * 16 + n]);
    float h = 0.f;
    const int base_r = b * T_;
    for (int t = 0; t < T_; t++) {
        int r = base_r + t;
        float d  = g_delta[(size_t)r * 1024 + s];
        float u  = g_XI[(size_t)r * 2048 + s];
        float Bv = g_Bmat[(size_t)r * 16384 + s * 16 + n];
        float Cv = g_Cmat[(size_t)r * 16384 + s * 16 + n];
        h = expf(d * A) * h + (d * u) * Bv;
        float p = h * Cv;
        p += __shfl_xor_sync(0xffffffffu, p, 1);
        p += __shfl_xor_sync(0xffffffffu, p, 2);
        p += __shfl_xor_sync(0xffffffffu, p, 4);
        p += __shfl_xor_sync(0xffffffffu, p, 8);
        if (n == 0) {
            size_t idx = (size_t)r * 1024 + s;
            g_y[idx] = p;
            __nv_bfloat16 hh = __float2bfloat16(p);
            g_yh[idx] = hh;
            g_yl[idx] = __float2bfloat16(p - __bfloat162float(hh));
        }
    }
}

// ---------------- RMS ----------------
__global__ void rms_kernel(const float* __restrict__ gg) {
    int r = blockIdx.x;
    const float* xin = g_yo + (size_t)r * 1024;
    float vals[4];
    float ss = 0.f;
#pragma unroll
    for (int j = 0; j < 4; j++) {
        int d = threadIdx.x + j * 256;
        float v = xin[d];
        vals[j] = v;
        ss += v * v;
    }
    ss = block_sum256(ss);
    float inv = 1.f / sqrtf(ss * (1.f / 1024.f) + EPS_);
#pragma unroll
    for (int j = 0; j < 4; j++) {
        int d = threadIdx.x + j * 256;
        g_s6[(size_t)r * 1024 + d] = gg[d] * vals[j] * inv;
    }
}

// ---------------- combine ----------------
__global__ void combine_kernel(const float* __restrict__ x, const float* __restrict__ gfg) {
    int r = blockIdx.x;
    float vals[4];
    float ss = 0.f;
#pragma unroll
    for (int j = 0; j < 4; j++) {
        int d = threadIdx.x + j * 256;
        size_t idx = (size_t)r * 1024 + d;
        float v = g_g1[idx] * g_s6[idx] + g_g2[idx] * g_glcm[idx];
        vals[j] = v;
        ss += v * v;
    }
    ss = block_sum256(ss);
    float inv = 1.f / sqrtf(ss * (1.f / 1024.f) + EPS_);
#pragma unroll
    for (int j = 0; j < 4; j++) {
        int d = threadIdx.x + j * 256;
        size_t idx = (size_t)r * 1024 + d;
        g_h[idx] = x[idx] + gfg[d] * vals[j] * inv;
    }
}

// ---------------- MoE routing ----------------
__global__ void zero_cnt_kernel() {
    if (threadIdx.x < E_) g_cnt[threadIdx.x] = 0;
}

__global__ void route_kernel(const float* __restrict__ Wg) {
    int warp = threadIdx.x >> 5, lane = threadIdx.x & 31;
    int token = blockIdx.x * 8 + warp;
    float acc[16];
#pragma unroll
    for (int e = 0; e < 16; e++) acc[e] = 0.f;
    const float* hrow = g_h + (size_t)token * 1024;
    for (int d = lane; d < 1024; d += 32) {
        float xv = hrow[d];
#pragma unroll
        for (int e = 0; e < 16; e++) acc[e] += xv * Wg[d * 16 + e];
    }
#pragma unroll
    for (int e = 0; e < 16; e++) {
#pragma unroll
        for (int o = 16; o; o >>= 1) acc[e] += __shfl_xor_sync(0xffffffffu, acc[e], o);
    }
    if (lane == 0) {
        float v0 = -1e30f; int i0 = 0;
#pragma unroll
        for (int e = 0; e < 16; e++) if (acc[e] > v0) { v0 = acc[e]; i0 = e; }
        float v1 = -1e30f; int i1 = 0;
#pragma unroll
        for (int e = 0; e < 16; e++) if (e != i0 && acc[e] > v1) { v1 = acc[e]; i1 = e; }
        float w0 = 1.f / (1.f + expf(v1 - v0));
        g_w[token * 2]     = w0;
        g_w[token * 2 + 1] = 1.f - w0;
        int p0 = atomicAdd(&g_cnt[i0], 1);
        g_list[i0 * 2048 + p0] = token * 2;
        int p1 = atomicAdd(&g_cnt[i1], 1);
        g_list[i1 * 2048 + p1] = token * 2 + 1;
    }
}

// ---------------- final ----------------
__global__ void final_kernel(float* __restrict__ out) {
    int idx = blockIdx.x * 256 + threadIdx.x;
    int r = idx >> 10, d = idx & 1023;
    out[idx] = g_h[idx] + g_e2[(size_t)r * 2048 + d] + g_e2[(size_t)r * 2048 + 1024 + d];
}

// ---------------- launch ----------------
extern "C" void kernel_launch(void* const* d_in, const int* /*in_sizes*/, int /*n_in*/,
                              void* d_out, int /*out_size*/) {
    const float* x    = (const float*)d_in[0];
    const float* sinp = (const float*)d_in[1];
    const float* cosp = (const float*)d_in[2];
    const float* Wp   = (const float*)d_in[3];
    const float* bp   = (const float*)d_in[4];
    const float* Wdw  = (const float*)d_in[5];
    const float* bdw  = (const float*)d_in[6];
    const float* glg  = (const float*)d_in[7];
    const float* Win  = (const float*)d_in[8];
    const float* bin  = (const float*)d_in[9];
    const float* Wd   = (const float*)d_in[10];
    const float* bd   = (const float*)d_in[11];
    const float* WB   = (const float*)d_in[12];
    const float* bB   = (const float*)d_in[13];
    const float* WC   = (const float*)d_in[14];
    const float* bC   = (const float*)d_in[15];
    const float* Alog = (const float*)d_in[16];
    const float* Wout = (const float*)d_in[17];
    const float* bout = (const float*)d_in[18];
    const float* s6g  = (const float*)d_in[19];
    const float* gfW1 = (const float*)d_in[20];
    const float* gfb1 = (const float*)d_in[21];
    const float* gfW2 = (const float*)d_in[22];
    const float* gfb2 = (const float*)d_in[23];
    const float* gfg  = (const float*)d_in[24];
    const float* Wg   = (const float*)d_in[25];
    const float* mW1  = (const float*)d_in[26];
    const float* mb1  = (const float*)d_in[27];
    const float* mW2  = (const float*)d_in[28];
    const float* mb2  = (const float*)d_in[29];
    float* out = (float*)d_out;

    cudaFuncSetAttribute(wgemm<0>, cudaFuncAttributeMaxDynamicSharedMemorySize, DSMEM);
    cudaFuncSetAttribute(wgemm<1>, cudaFuncAttributeMaxDynamicSharedMemorySize, DSMEM);
    cudaFuncSetAttribute(wgemm<2>, cudaFuncAttributeMaxDynamicSharedMemorySize, DSMEM);

    float *pP, *pXI, *pDelta, *pB, *pC, *pYO, *pG1, *pG2;
    cudaGetSymbolAddress((void**)&pP,     g_P);
    cudaGetSymbolAddress((void**)&pXI,    g_XI);
    cudaGetSymbolAddress((void**)&pDelta, g_delta);
    cudaGetSymbolAddress((void**)&pB,     g_Bmat);
    cudaGetSymbolAddress((void**)&pC,     g_Cmat);
    cudaGetSymbolAddress((void**)&pYO,    g_yo);
    cudaGetSymbolAddress((void**)&pG1,    g_g1);
    cudaGetSymbolAddress((void**)&pG2,    g_g2);

    __nv_bfloat16 *xh, *xl, *XIh, *XIl, *yh, *yl;
    cudaGetSymbolAddress((void**)&xh,  g_xh);  cudaGetSymbolAddress((void**)&xl,  g_xl);
    cudaGetSymbolAddress((void**)&XIh, g_XIh); cudaGetSymbolAddress((void**)&XIl, g_XIl);
    cudaGetSymbolAddress((void**)&yh,  g_yh);  cudaGetSymbolAddress((void**)&yl,  g_yl);

    // 0) x -> bf16 hi/lo mirror
    convx_kernel<<<1024, 256>>>(x);

    // 1+2) P (z=0), XI (z=1, emits bf16 mirrors)
    wgemm<0><<<dim3(8, 16, 2), 256, DSMEM>>>(xh, xl, Wp, Win, bp, bin, pP, pXI, XIh, XIl, 2048, 1024);
    // 3) rotary + glcm
    rotary_kernel<<<BT, 256>>>(sinp, cosp);
    glcm_kernel<<<BT, 256>>>(Wdw, bdw, glg);
    // 5) delta = softplus(XI @ Wd + bd)
    wgemm<1><<<dim3(8, 8, 1), 256, DSMEM>>>(XIh, XIl, Wd, Wd, bd, bd, pDelta, pDelta, nullptr, nullptr, 1024, 2048);
    // 6+7) B (z=0) and C (z=1) projections merged
    wgemm<0><<<dim3(8, 128, 2), 256, DSMEM>>>(XIh, XIl, WB, WC, bB, bC, pB, pC, nullptr, nullptr, 16384, 2048);
    // 8) scan
    scan_kernel<<<128, 256>>>(Alog);
    // 9) yo = y @ Wout + bout ; rms
    wgemm<0><<<dim3(8, 8, 1), 256, DSMEM>>>(yh, yl, Wout, Wout, bout, bout, pYO, pYO, nullptr, nullptr, 1024, 1024);
    rms_kernel<<<BT, 256>>>(s6g);
    // 10) gates g1 (z=0), g2 (z=1)
    wgemm<2><<<dim3(8, 8, 2), 256, DSMEM>>>(xh, xl, gfW1, gfW2, gfb1, gfb2, pG1, pG2, nullptr, nullptr, 1024, 1024);
    // 11) combine
    combine_kernel<<<BT, 256>>>(x, gfg);
    // 12) routing
    zero_cnt_kernel<<<1, 32>>>();
    route_kernel<<<128, 256>>>(Wg);
    // 13/14) expert FFN — single-pass fp16
    moe_fp16_kernel<1><<<dim3(16, 32, 16), 256>>>(mW1, mb1);
    moe_fp16_kernel<2><<<dim3(16, 8, 16), 256>>>(mW2, mb2);
    // 15) final
    final_kernel<<<4096, 256>>>(out);
}

// round 14
// speedup vs baseline: 4.6031x; 1.2573x over previous
#include <cuda_runtime.h>
#include <cuda_bf16.h>
#include <cuda_fp16.h>
#include <math.h>
#include <stdint.h>

// ---------------- constants ----------------
constexpr int E_  = 16;
constexpr int T_  = 512;
constexpr int BT  = 1024;   // B*T
constexpr float EPS_ = 1e-8f;

// ---------------- f32 scratch ----------------
__device__ float g_P    [BT * 2048];
__device__ float g_XI   [BT * 2048];
__device__ float g_XR   [BT * 1024];
__device__ float g_glcm [BT * 1024];
__device__ float g_delta[BT * 1024];
__device__ float g_Bmat [BT * 16384];
__device__ float g_Cmat [BT * 16384];
__device__ float g_y    [BT * 1024];
__device__ float g_yo   [BT * 1024];
__device__ float g_s6   [BT * 1024];
__device__ float g_g1   [BT * 1024];
__device__ float g_g2   [BT * 1024];
__device__ float g_h    [BT * 1024];
__device__ float g_e2   [2 * BT * 1024];
__device__ int   g_cnt  [E_];
__device__ int   g_list [E_ * 2048];
__device__ float g_w    [2 * BT];

// ---------------- fp16 MoE intermediate ----------------
__device__ __half g_e1h [2 * BT * 4096];

// ---------------- bf16 hi/lo activation mirrors (dense path) ----------------
__device__ __nv_bfloat16 g_xh [BT * 1024], g_xl [BT * 1024];
__device__ __nv_bfloat16 g_XIh[BT * 2048], g_XIl[BT * 2048];
__device__ __nv_bfloat16 g_yh [BT * 1024], g_yl [BT * 1024];

// ---------------- helpers ----------------
__device__ __forceinline__ float sigmoidf_(float x) { return 1.f / (1.f + expf(-x)); }

__device__ __forceinline__ float block_sum256(float v) {
    __shared__ float sh[8];
    int lane = threadIdx.x & 31, w = threadIdx.x >> 5;
#pragma unroll
    for (int o = 16; o; o >>= 1) v += __shfl_xor_sync(0xffffffffu, v, o);
    if (lane == 0) sh[w] = v;
    __syncthreads();
    float s = 0.f;
#pragma unroll
    for (int i = 0; i < 8; i++) s += sh[i];
    return s;
}

__device__ __forceinline__ uint32_t smem_u32(const void* p) {
    return (uint32_t)__cvta_generic_to_shared(p);
}

__device__ __forceinline__ void ldsm_x4(uint32_t& r0, uint32_t& r1, uint32_t& r2, uint32_t& r3, uint32_t addr) {
    asm volatile("ldmatrix.sync.aligned.m8n8.x4.shared.b16 {%0,%1,%2,%3}, [%4];"
        : "=r"(r0), "=r"(r1), "=r"(r2), "=r"(r3) : "r"(addr));
}
__device__ __forceinline__ void ldsm_x4_t(uint32_t& r0, uint32_t& r1, uint32_t& r2, uint32_t& r3, uint32_t addr) {
    asm volatile("ldmatrix.sync.aligned.m8n8.x4.trans.shared.b16 {%0,%1,%2,%3}, [%4];"
        : "=r"(r0), "=r"(r1), "=r"(r2), "=r"(r3) : "r"(addr));
}
__device__ __forceinline__ void mma_bf16(float* c, const uint32_t* a, const uint32_t* b) {
    asm volatile("mma.sync.aligned.m16n8k16.row.col.f32.bf16.bf16.f32 "
        "{%0,%1,%2,%3}, {%4,%5,%6,%7}, {%8,%9}, {%0,%1,%2,%3};"
        : "+f"(c[0]), "+f"(c[1]), "+f"(c[2]), "+f"(c[3])
        : "r"(a[0]), "r"(a[1]), "r"(a[2]), "r"(a[3]), "r"(b[0]), "r"(b[1]));
}
__device__ __forceinline__ void mma_f16(float* c, const uint32_t* a, const uint32_t* b) {
    asm volatile("mma.sync.aligned.m16n8k16.row.col.f32.f16.f16.f32 "
        "{%0,%1,%2,%3}, {%4,%5,%6,%7}, {%8,%9}, {%0,%1,%2,%3};"
        : "+f"(c[0]), "+f"(c[1]), "+f"(c[2]), "+f"(c[3])
        : "r"(a[0]), "r"(a[1]), "r"(a[2]), "r"(a[3]), "r"(b[0]), "r"(b[1]));
}
__device__ __forceinline__ void cvt_split16(const float* v, uint32_t* hi, uint32_t* lo) {
#pragma unroll
    for (int i = 0; i < 8; i++) {
        float x0 = v[2 * i], x1 = v[2 * i + 1];
        __nv_bfloat16 h0 = __float2bfloat16(x0), h1 = __float2bfloat16(x1);
        float r0 = x0 - __bfloat162float(h0), r1 = x1 - __bfloat162float(h1);
        __nv_bfloat16 l0 = __float2bfloat16(r0), l1 = __float2bfloat16(r1);
        hi[i] = ((uint32_t)__bfloat16_as_ushort(h1) << 16) | __bfloat16_as_ushort(h0);
        lo[i] = ((uint32_t)__bfloat16_as_ushort(l1) << 16) | __bfloat16_as_ushort(l0);
    }
}
__device__ __forceinline__ void cvt_h16(const float* v, uint32_t* h) {
#pragma unroll
    for (int i = 0; i < 8; i++) {
        __half2 p = __floats2half2_rn(v[2 * i], v[2 * i + 1]);
        h[i] = *(uint32_t*)&p;
    }
}

__device__ __forceinline__ void cp16(uint32_t dst, const void* src) {
    asm volatile("cp.async.cg.shared.global [%0], [%1], 16;" :: "r"(dst), "l"(src));
}
#define CP_COMMIT() asm volatile("cp.async.commit_group;" ::: "memory")
#define CP_WAIT1()  asm volatile("cp.async.wait_group 1;" ::: "memory")

// ============================================================================
// Dense GEMM, 3-way z-merged: per-z A/W/bias/C/N/EPI. Shared K.
// C[M,Nz] = Az[M,K] @ Wz[K,Nz] + bz.  EPI runtime: 0 none, 1 softplus, 2 sigmoid.
// z blocks with nBase >= Nz early-return (used to ride delta on the B/C wave).
// CTA 128x128, KTILE 32, 256 threads = 8 warps (2m x 4n).
// ============================================================================
constexpr int AP = 10240;
constexpr int BP = 8704;
constexpr int STG = 2 * AP + 2 * BP;
constexpr int DSMEM = 2 * STG;

__global__ __launch_bounds__(256)
void wgemm3(const __nv_bfloat16* __restrict__ A0h, const __nv_bfloat16* __restrict__ A0l,
            const __nv_bfloat16* __restrict__ A1h, const __nv_bfloat16* __restrict__ A1l,
            const __nv_bfloat16* __restrict__ A2h, const __nv_bfloat16* __restrict__ A2l,
            const float* __restrict__ W0, const float* __restrict__ W1, const float* __restrict__ W2,
            const float* __restrict__ b0, const float* __restrict__ b1, const float* __restrict__ b2,
            float* __restrict__ C0, float* __restrict__ C1, float* __restrict__ C2,
            int N0, int N1, int N2, int e0, int e1, int e2,
            __nv_bfloat16* __restrict__ Ch, __nv_bfloat16* __restrict__ Cl,
            int K) {
    extern __shared__ char smem[];
    const uint32_t sb = smem_u32(smem);

    const int z = blockIdx.z;
    const __nv_bfloat16* __restrict__ Ah = (z == 0) ? A0h : (z == 1) ? A1h : A2h;
    const __nv_bfloat16* __restrict__ Al = (z == 0) ? A0l : (z == 1) ? A1l : A2l;
    const float* __restrict__ W    = (z == 0) ? W0 : (z == 1) ? W1 : W2;
    const float* __restrict__ bias = (z == 0) ? b0 : (z == 1) ? b1 : b2;
    float* __restrict__ C          = (z == 0) ? C0 : (z == 1) ? C1 : C2;
    const int Ntot = (z == 0) ? N0 : (z == 1) ? N1 : N2;
    const int EPI  = (z == 0) ? e0 : (z == 1) ? e1 : e2;
    const bool bout = (Ch != nullptr) && (z == 1);

    const int nBase = blockIdx.y * 128;
    if (nBase >= Ntot) return;   // inactive tile (merged small-N member)

    const int tid = threadIdx.x;
    const int warp = tid >> 5, lane = tid & 31;
    const int wm = warp & 1, wn = warp >> 1;
    const int mBase = blockIdx.x * 128;
    const int wmBase = wm * 64, wnBase = wn * 32;

    const int S = K >> 5;

    auto load_A = [&](int s, int b) {
        const int k0 = s << 5;
        const uint32_t base = sb + b * STG;
#pragma unroll
        for (int i = 0; i < 2; i++) {
            int c = i * 256 + tid;
            int r = c >> 2, c4 = c & 3;
            uint32_t dst = base + (uint32_t)(r * 80 + c4 * 16);
            cp16(dst,      Ah + (size_t)(mBase + r) * K + k0 + c4 * 8);
            cp16(dst + AP, Al + (size_t)(mBase + r) * K + k0 + c4 * 8);
        }
    };

    const int wr = tid >> 3, wc = (tid & 7) * 16;
    float wreg[16];
    auto ldg_W = [&](int s) {
        const float* src = W + (size_t)((s << 5) + wr) * Ntot + nBase + wc;
        *(float4*)&wreg[0]  = *(const float4*)(src);
        *(float4*)&wreg[4]  = *(const float4*)(src + 4);
        *(float4*)&wreg[8]  = *(const float4*)(src + 8);
        *(float4*)&wreg[12] = *(const float4*)(src + 12);
    };
    auto sts_W = [&](int b) {
        uint32_t hi[8], lo[8];
        cvt_split16(wreg, hi, lo);
        const uint32_t off = b * STG + 2 * AP + (uint32_t)(wr * 272 + wc * 2);
        *(uint4*)(smem + off)           = *(uint4*)&hi[0];
        *(uint4*)(smem + off + 16)      = *(uint4*)&hi[4];
        *(uint4*)(smem + off + BP)      = *(uint4*)&lo[0];
        *(uint4*)(smem + off + BP + 16) = *(uint4*)&lo[4];
    };

    float acc[4][4][4] = {};

    const int lrow = lane & 15;
    const int lcolB = ((lane >> 4) << 3) * 2;

    ldg_W(0);
    load_A(0, 0); CP_COMMIT();
    load_A(1, 1); CP_COMMIT();

    for (int s = 0; s < S; s++) {
        const int b = s & 1;
        sts_W(b);
        if (s + 1 < S) ldg_W(s + 1);
        CP_WAIT1();
        __syncthreads();

        const uint32_t base = sb + b * STG;
        const uint32_t aH = base + (uint32_t)((wmBase + lrow) * 80) + lcolB;
        const uint32_t aL = aH + AP;
        const uint32_t bH = base + 2 * AP + (uint32_t)(lrow * 272) + (uint32_t)(wnBase * 2) + lcolB;
        const uint32_t bL = bH + BP;

#pragma unroll
        for (int chunk = 0; chunk < 2; chunk++) {
            uint32_t Afh[4][4], Afl[4][4], Bfh[4][2], Bfl[4][2];
#pragma unroll
            for (int mi = 0; mi < 4; mi++) {
                ldsm_x4(Afh[mi][0], Afh[mi][1], Afh[mi][2], Afh[mi][3],
                        aH + mi * (16 * 80) + chunk * 32);
                ldsm_x4(Afl[mi][0], Afl[mi][1], Afl[mi][2], Afl[mi][3],
                        aL + mi * (16 * 80) + chunk * 32);
            }
#pragma unroll
            for (int g = 0; g < 2; g++) {
                uint32_t r0, r1, r2, r3;
                ldsm_x4_t(r0, r1, r2, r3, bH + chunk * (16 * 272) + g * 32);
                Bfh[2 * g][0] = r0; Bfh[2 * g][1] = r1; Bfh[2 * g + 1][0] = r2; Bfh[2 * g + 1][1] = r3;
                ldsm_x4_t(r0, r1, r2, r3, bL + chunk * (16 * 272) + g * 32);
                Bfl[2 * g][0] = r0; Bfl[2 * g][1] = r1; Bfl[2 * g + 1][0] = r2; Bfl[2 * g + 1][1] = r3;
            }
#pragma unroll
            for (int mi = 0; mi < 4; mi++)
#pragma unroll
                for (int ni = 0; ni < 4; ni++) {
                    mma_bf16(acc[mi][ni], Afh[mi], Bfh[ni]);
                    mma_bf16(acc[mi][ni], Afh[mi], Bfl[ni]);
                    mma_bf16(acc[mi][ni], Afl[mi], Bfh[ni]);
                }
        }
        __syncthreads();
        if (s + 2 < S) load_A(s + 2, b);
        CP_COMMIT();
    }

    const int lr = lane >> 2, lc = (lane & 3) * 2;
#pragma unroll
    for (int mi = 0; mi < 4; mi++) {
        size_t row0 = (size_t)(mBase + wmBase + mi * 16 + lr);
#pragma unroll
        for (int ni = 0; ni < 4; ni++) {
            int col = nBase + wnBase + ni * 8 + lc;
            float bb0 = bias[col], bb1 = bias[col + 1];
            float v[4] = {acc[mi][ni][0] + bb0, acc[mi][ni][1] + bb1,
                          acc[mi][ni][2] + bb0, acc[mi][ni][3] + bb1};
            if (EPI == 1) {
#pragma unroll
                for (int q = 0; q < 4; q++)
                    v[q] = fmaxf(v[q], 0.f) + log1pf(expf(-fabsf(v[q])));
            } else if (EPI == 2) {
#pragma unroll
                for (int q = 0; q < 4; q++) v[q] = sigmoidf_(v[q]);
            }
            size_t i0 = row0 * Ntot + col;
            size_t i1 = (row0 + 8) * Ntot + col;
            *(float2*)(C + i0) = make_float2(v[0], v[1]);
            *(float2*)(C + i1) = make_float2(v[2], v[3]);
            if (bout) {
                __nv_bfloat16 h0 = __float2bfloat16(v[0]), h1 = __float2bfloat16(v[1]);
                __nv_bfloat16 h2 = __float2bfloat16(v[2]), h3 = __float2bfloat16(v[3]);
                Ch[i0] = h0; Ch[i0 + 1] = h1; Ch[i1] = h2; Ch[i1 + 1] = h3;
                Cl[i0]     = __float2bfloat16(v[0] - __bfloat162float(h0));
                Cl[i0 + 1] = __float2bfloat16(v[1] - __bfloat162float(h1));
                Cl[i1]     = __float2bfloat16(v[2] - __bfloat162float(h2));
                Cl[i1 + 1] = __float2bfloat16(v[3] - __bfloat162float(h3));
            }
        }
    }
}

// ============================================================================
// MoE gather-GEMM, single-pass fp16 (verified R12)
// ============================================================================
constexpr int MA_STR = 40;
constexpr int MB_STR = 136;

template <int PHASE>
__global__ __launch_bounds__(256)
void moe_fp16_kernel(const float* __restrict__ Wall, const float* __restrict__ ball) {
    constexpr int K = (PHASE == 1) ? 1024 : 4096;
    constexpr int N = (PHASE == 1) ? 4096 : 1024;
    const int e = blockIdx.z;
    const int mc = g_cnt[e];
    const int m0 = blockIdx.x * 128;
    if (m0 >= mc) return;
    const float* W = Wall + (size_t)e * K * N;
    const float* bias = ball + (size_t)e * N;

    __shared__ int rows[128];
    __shared__ __half sA[128][MA_STR];
    __shared__ __half sB[32][MB_STR];

    const int tid = threadIdx.x;
    const int warp = tid >> 5, lane = tid & 31;
    const int wm = warp & 1, wn = warp >> 1;
    const int nBase = blockIdx.y * 128;
    const int wmBase = wm * 64, wnBase = wn * 32;

    if (tid < 128) {
        int m = m0 + tid;
        rows[tid] = (m < mc) ? g_list[e * 2048 + m] : -1;
    }
    __syncthreads();

    const int arow = tid >> 1, acb = (tid & 1) * 16;
    const int brow = tid >> 3, bcb = (tid & 7) * 16;
    const int arid = rows[arow];

    const int lrow = lane & 15;
    const int lcol = (lane >> 4) << 3;
    const uint32_t aBase = smem_u32(&sA[wmBase + lrow][lcol]);
    const uint32_t bBase = smem_u32(&sB[lrow][wnBase + lcol]);

    float acc[4][4][4] = {};

    for (int k0 = 0; k0 < K; k0 += 32) {
        if (PHASE == 1) {
            float av[16];
            if (arid >= 0) {
                const float* ap = g_h + (size_t)(arid >> 1) * 1024 + k0 + acb;
                *(float4*)&av[0]  = *(const float4*)(ap);
                *(float4*)&av[4]  = *(const float4*)(ap + 4);
                *(float4*)&av[8]  = *(const float4*)(ap + 8);
                *(float4*)&av[12] = *(const float4*)(ap + 12);
            } else {
#pragma unroll
                for (int i = 0; i < 16; i++) av[i] = 0.f;
            }
            uint32_t hw[8];
            cvt_h16(av, hw);
            *(uint4*)&sA[arow][acb]     = *(uint4*)&hw[0];
            *(uint4*)&sA[arow][acb + 8] = *(uint4*)&hw[4];
        } else {
            uint4 v0 = make_uint4(0, 0, 0, 0), v1 = make_uint4(0, 0, 0, 0);
            if (arid >= 0) {
                const __half* ap = g_e1h + (size_t)arid * 4096 + k0 + acb;
                v0 = *(const uint4*)(ap);
                v1 = *(const uint4*)(ap + 8);
            }
            *(uint4*)&sA[arow][acb]     = v0;
            *(uint4*)&sA[arow][acb + 8] = v1;
        }
        {
            const float* bp = W + (size_t)(k0 + brow) * N + nBase + bcb;
            float bv[16];
            *(float4*)&bv[0]  = *(const float4*)(bp);
            *(float4*)&bv[4]  = *(const float4*)(bp + 4);
            *(float4*)&bv[8]  = *(const float4*)(bp + 8);
            *(float4*)&bv[12] = *(const float4*)(bp + 12);
            uint32_t hw[8];
            cvt_h16(bv, hw);
            *(uint4*)&sB[brow][bcb]     = *(uint4*)&hw[0];
            *(uint4*)&sB[brow][bcb + 8] = *(uint4*)&hw[4];
        }
        __syncthreads();

#pragma unroll
        for (int chunk = 0; chunk < 2; chunk++) {
            uint32_t Af[4][4], Bf[4][2];
#pragma unroll
            for (int mi = 0; mi < 4; mi++)
                ldsm_x4(Af[mi][0], Af[mi][1], Af[mi][2], Af[mi][3],
                        aBase + mi * (16 * MA_STR * 2) + chunk * 32);
#pragma unroll
            for (int g = 0; g < 2; g++) {
                uint32_t r0, r1, r2, r3;
                ldsm_x4_t(r0, r1, r2, r3, bBase + chunk * (16 * MB_STR * 2) + g * 32);
                Bf[2 * g][0] = r0; Bf[2 * g][1] = r1; Bf[2 * g + 1][0] = r2; Bf[2 * g + 1][1] = r3;
            }
#pragma unroll
            for (int mi = 0; mi < 4; mi++)
#pragma unroll
                for (int ni = 0; ni < 4; ni++)
                    mma_f16(acc[mi][ni], Af[mi], Bf[ni]);
        }
        __syncthreads();
    }

    const int lr = lane >> 2, lc = (lane & 3) * 2;
#pragma unroll
    for (int mi = 0; mi < 4; mi++) {
        int a0 = rows[wmBase + mi * 16 + lr];
        int a1 = rows[wmBase + mi * 16 + lr + 8];
#pragma unroll
        for (int ni = 0; ni < 4; ni++) {
            int col = nBase + wnBase + ni * 8 + lc;
            float b0 = bias[col], b1 = bias[col + 1];
            float v00 = acc[mi][ni][0] + b0, v01 = acc[mi][ni][1] + b1;
            float v10 = acc[mi][ni][2] + b0, v11 = acc[mi][ni][3] + b1;
            if (PHASE == 1) {
                v00 *= sigmoidf_(v00); v01 *= sigmoidf_(v01);
                v10 *= sigmoidf_(v10); v11 *= sigmoidf_(v11);
                if (a0 >= 0) {
                    __half2 p = __floats2half2_rn(v00, v01);
                    *(__half2*)(g_e1h + (size_t)a0 * 4096 + col) = p;
                }
                if (a1 >= 0) {
                    __half2 p = __floats2half2_rn(v10, v11);
                    *(__half2*)(g_e1h + (size_t)a1 * 4096 + col) = p;
                }
            } else {
                float w0 = (a0 >= 0) ? g_w[a0] : 0.f;
                float w1 = (a1 >= 0) ? g_w[a1] : 0.f;
                if (a0 >= 0) *(float2*)(g_e2 + (size_t)a0 * 1024 + col) = make_float2(v00 * w0, v01 * w0);
                if (a1 >= 0) *(float2*)(g_e2 + (size_t)a1 * 1024 + col) = make_float2(v10 * w1, v11 * w1);
            }
        }
    }
}

// ---------------- x -> bf16 hi/lo ----------------
__global__ void convx_kernel(const float* __restrict__ x) {
    int i = (blockIdx.x * 256 + threadIdx.x) * 4;
    float4 v = *(const float4*)(x + i);
    float a[4] = {v.x, v.y, v.z, v.w};
#pragma unroll
    for (int j = 0; j < 4; j++) {
        __nv_bfloat16 h = __float2bfloat16(a[j]);
        g_xh[i + j] = h;
        g_xl[i + j] = __float2bfloat16(a[j] - __bfloat162float(h));
    }
}

// ---------------- rotary ----------------
__global__ void rotary_kernel(const float* __restrict__ sinp, const float* __restrict__ cosp) {
    int r = blockIdx.x;
    int t = r & (T_ - 1);
    const float* pr = g_P + (size_t)r * 2048;
    float* xr = g_XR + (size_t)r * 1024;
    for (int i = threadIdx.x; i < 512; i += 256) {
        float c = cosp[t * 512 + i], s = sinp[t * 512 + i];
        float a0 = pr[2 * i], a1 = pr[2 * i + 1];
        xr[2 * i]     = a0 * c - a1 * s;
        xr[2 * i + 1] = a0 * s + a1 * c;
    }
}

// ---------------- dwconv + gate + RMS -> glcm ----------------
__global__ void glcm_kernel(const float* __restrict__ Wdw, const float* __restrict__ bdw,
                            const float* __restrict__ gg) {
    int r = blockIdx.x;
    int b = r >> 9, t = r & 511;
    float vals[4];
    float ss = 0.f;
#pragma unroll
    for (int j = 0; j < 4; j++) {
        int d = threadIdx.x + j * 256;
        float conv = bdw[d];
#pragma unroll
        for (int k = 0; k < 7; k++) {
            int tt = t + k - 3;
            if (tt >= 0 && tt < T_)
                conv += g_XR[(size_t)(b * T_ + tt) * 1024 + d] * Wdw[k * 1024 + d];
        }
        float xb = g_P[(size_t)r * 2048 + 1024 + d];
        float v = conv * sigmoidf_(conv) * sigmoidf_(xb);
        vals[j] = v;
        ss += v * v;
    }
    ss = block_sum256(ss);
    float inv = 1.f / sqrtf(ss * (1.f / 1024.f) + EPS_);
#pragma unroll
    for (int j = 0; j < 4; j++) {
        int d = threadIdx.x + j * 256;
        g_glcm[(size_t)r * 1024 + d] = gg[d] * vals[j] * inv;
    }
}

// ---------------- sequential S6 scan with t+1 register prefetch ----------------
__global__ void scan_kernel(const float* __restrict__ Alog) {
    int gw = (blockIdx.x * blockDim.x + threadIdx.x) >> 5;
    int lane = threadIdx.x & 31;
    int b = gw >> 9;
    int spair = gw & 511;
    int half = lane >> 4, n = lane & 15;
    int s = spair * 2 + half;
    float A = -expf(Alog[s * 16 + n]);
    float h = 0.f;
    int r = b * T_;

    const float* dp = g_delta + s;
    const float* up = g_XI + s;
    const float* Bp = g_Bmat + s * 16 + n;
    const float* Cp = g_Cmat + s * 16 + n;

    float d  = dp[(size_t)r * 1024];
    float u  = up[(size_t)r * 2048];
    float Bv = Bp[(size_t)r * 16384];
    float Cv = Cp[(size_t)r * 16384];

    for (int t = 0; t < T_; t++) {
        float dn = 0.f, un = 0.f, Bn = 0.f, Cn = 0.f;
        if (t + 1 < T_) {
            size_t r1 = (size_t)(r + 1);
            dn = dp[r1 * 1024];
            un = up[r1 * 2048];
            Bn = Bp[r1 * 16384];
            Cn = Cp[r1 * 16384];
        }
        h = expf(d * A) * h + (d * u) * Bv;
        float p = h * Cv;
        p += __shfl_xor_sync(0xffffffffu, p, 1);
        p += __shfl_xor_sync(0xffffffffu, p, 2);
        p += __shfl_xor_sync(0xffffffffu, p, 4);
        p += __shfl_xor_sync(0xffffffffu, p, 8);
        if (n == 0) {
            size_t idx = (size_t)r * 1024 + s;
            g_y[idx] = p;
            __nv_bfloat16 hh = __float2bfloat16(p);
            g_yh[idx] = hh;
            g_yl[idx] = __float2bfloat16(p - __bfloat162float(hh));
        }
        d = dn; u = un; Bv = Bn; Cv = Cn;
        r++;
    }
}

// ---------------- RMS ----------------
__global__ void rms_kernel(const float* __restrict__ gg) {
    int r = blockIdx.x;
    const float* xin = g_yo + (size_t)r * 1024;
    float vals[4];
    float ss = 0.f;
#pragma unroll
    for (int j = 0; j < 4; j++) {
        int d = threadIdx.x + j * 256;
        float v = xin[d];
        vals[j] = v;
        ss += v * v;
    }
    ss = block_sum256(ss);
    float inv = 1.f / sqrtf(ss * (1.f / 1024.f) + EPS_);
#pragma unroll
    for (int j = 0; j < 4; j++) {
        int d = threadIdx.x + j * 256;
        g_s6[(size_t)r * 1024 + d] = gg[d] * vals[j] * inv;
    }
}

// ---------------- combine ----------------
__global__ void combine_kernel(const float* __restrict__ x, const float* __restrict__ gfg) {
    int r = blockIdx.x;
    float vals[4];
    float ss = 0.f;
#pragma unroll
    for (int j = 0; j < 4; j++) {
        int d = threadIdx.x + j * 256;
        size_t idx = (size_t)r * 1024 + d;
        float v = g_g1[idx] * g_s6[idx] + g_g2[idx] * g_glcm[idx];
        vals[j] = v;
        ss += v * v;
    }
    ss = block_sum256(ss);
    float inv = 1.f / sqrtf(ss * (1.f / 1024.f) + EPS_);
#pragma unroll
    for (int j = 0; j < 4; j++) {
        int d = threadIdx.x + j * 256;
        size_t idx = (size_t)r * 1024 + d;
        g_h[idx] = x[idx] + gfg[d] * vals[j] * inv;
    }
}

// ---------------- MoE routing ----------------
__global__ void zero_cnt_kernel() {
    if (threadIdx.x < E_) g_cnt[threadIdx.x] = 0;
}

__global__ void route_kernel(const float* __restrict__ Wg) {
    int warp = threadIdx.x >> 5, lane = threadIdx.x & 31;
    int token = blockIdx.x * 8 + warp;
    float acc[16];
#pragma unroll
    for (int e = 0; e < 16; e++) acc[e] = 0.f;
    const float* hrow = g_h + (size_t)token * 1024;
    for (int d = lane; d < 1024; d += 32) {
        float xv = hrow[d];
#pragma unroll
        for (int e = 0; e < 16; e++) acc[e] += xv * Wg[d * 16 + e];
    }
#pragma unroll
    for (int e = 0; e < 16; e++) {
#pragma unroll
        for (int o = 16; o; o >>= 1) acc[e] += __shfl_xor_sync(0xffffffffu, acc[e], o);
    }
    if (lane == 0) {
        float v0 = -1e30f; int i0 = 0;
#pragma unroll
        for (int e = 0; e < 16; e++) if (acc[e] > v0) { v0 = acc[e]; i0 = e; }
        float v1 = -1e30f; int i1 = 0;
#pragma unroll
        for (int e = 0; e < 16; e++) if (e != i0 && acc[e] > v1) { v1 = acc[e]; i1 = e; }
        float w0 = 1.f / (1.f + expf(v1 - v0));
        g_w[token * 2]     = w0;
        g_w[token * 2 + 1] = 1.f - w0;
        int p0 = atomicAdd(&g_cnt[i0], 1);
        g_list[i0 * 2048 + p0] = token * 2;
        int p1 = atomicAdd(&g_cnt[i1], 1);
        g_list[i1 * 2048 + p1] = token * 2 + 1;
    }
}

// ---------------- final ----------------
__global__ void final_kernel(float* __restrict__ out) {
    int idx = blockIdx.x * 256 + threadIdx.x;
    int r = idx >> 10, d = idx & 1023;
    out[idx] = g_h[idx] + g_e2[(size_t)r * 2048 + d] + g_e2[(size_t)r * 2048 + 1024 + d];
}

// ---------------- launch (single stream — streams are banned by the guard) ----
extern "C" void kernel_launch(void* const* d_in, const int* /*in_sizes*/, int /*n_in*/,
                              void* d_out, int /*out_size*/) {
    const float* x    = (const float*)d_in[0];
    const float* sinp = (const float*)d_in[1];
    const float* cosp = (const float*)d_in[2];
    const float* Wp   = (const float*)d_in[3];
    const float* bp   = (const float*)d_in[4];
    const float* Wdw  = (const float*)d_in[5];
    const float* bdw  = (const float*)d_in[6];
    const float* glg  = (const float*)d_in[7];
    const float* Win  = (const float*)d_in[8];
    const float* bin  = (const float*)d_in[9];
    const float* Wd   = (const float*)d_in[10];
    const float* bd   = (const float*)d_in[11];
    const float* WB   = (const float*)d_in[12];
    const float* bB   = (const float*)d_in[13];
    const float* WC   = (const float*)d_in[14];
    const float* bC   = (const float*)d_in[15];
    const float* Alog = (const float*)d_in[16];
    const float* Wout = (const float*)d_in[17];
    const float* bout = (const float*)d_in[18];
    const float* s6g  = (const float*)d_in[19];
    const float* gfW1 = (const float*)d_in[20];
    const float* gfb1 = (const float*)d_in[21];
    const float* gfW2 = (const float*)d_in[22];
    const float* gfb2 = (const float*)d_in[23];
    const float* gfg  = (const float*)d_in[24];
    const float* Wg   = (const float*)d_in[25];
    const float* mW1  = (const float*)d_in[26];
    const float* mb1  = (const float*)d_in[27];
    const float* mW2  = (const float*)d_in[28];
    const float* mb2  = (const float*)d_in[29];
    float* out = (float*)d_out;

    cudaFuncSetAttribute(wgemm3, cudaFuncAttributeMaxDynamicSharedMemorySize, DSMEM);

    float *pP, *pXI, *pDelta, *pB, *pC, *pYO, *pG1, *pG2;
    cudaGetSymbolAddress((void**)&pP,     g_P);
    cudaGetSymbolAddress((void**)&pXI,    g_XI);
    cudaGetSymbolAddress((void**)&pDelta, g_delta);
    cudaGetSymbolAddress((void**)&pB,     g_Bmat);
    cudaGetSymbolAddress((void**)&pC,     g_Cmat);
    cudaGetSymbolAddress((void**)&pYO,    g_yo);
    cudaGetSymbolAddress((void**)&pG1,    g_g1);
    cudaGetSymbolAddress((void**)&pG2,    g_g2);

    __nv_bfloat16 *xh, *xl, *XIh, *XIl, *yh, *yl;
    cudaGetSymbolAddress((void**)&xh,  g_xh);  cudaGetSymbolAddress((void**)&xl,  g_xl);
    cudaGetSymbolAddress((void**)&XIh, g_XIh); cudaGetSymbolAddress((void**)&XIl, g_XIl);
    cudaGetSymbolAddress((void**)&yh,  g_yh);  cudaGetSymbolAddress((void**)&yl,  g_yl);

    // 0) x -> bf16 hi/lo mirror
    convx_kernel<<<1024, 256>>>(x);

    // 1+2) P (z=0) + XI (z=1, emits bf16 mirrors)
    wgemm3<<<dim3(8, 16, 2), 256, DSMEM>>>(
        xh, xl, xh, xl, xh, xl,
        Wp, Win, Win, bp, bin, bin, pP, pXI, pXI,
        2048, 2048, 2048, 0, 0, 0, XIh, XIl, 1024);

    // 3) rotary + glcm (need P only)
    rotary_kernel<<<BT, 256>>>(sinp, cosp);
    glcm_kernel<<<BT, 256>>>(Wdw, bdw, glg);

    // 5+6+7) B (z=0) + C (z=1) + delta (z=2, softplus, N=1024 -> y>=8 blocks idle)
    wgemm3<<<dim3(8, 128, 3), 256, DSMEM>>>(
        XIh, XIl, XIh, XIl, XIh, XIl,
        WB, WC, Wd, bB, bC, bd, pB, pC, pDelta,
        16384, 16384, 1024, 0, 0, 1, nullptr, nullptr, 2048);

    // 8) scan
    scan_kernel<<<128, 256>>>(Alog);

    // 9+10) g1 (z=0, sigmoid) + g2 (z=1, sigmoid) + yo (z=2, none) in one wave
    wgemm3<<<dim3(8, 8, 3), 256, DSMEM>>>(
        xh, xl, xh, xl, yh, yl,
        gfW1, gfW2, Wout, gfb1, gfb2, bout, pG1, pG2, pYO,
        1024, 1024, 1024, 2, 2, 0, nullptr, nullptr, 1024);
    rms_kernel<<<BT, 256>>>(s6g);

    // 11) combine
    combine_kernel<<<BT, 256>>>(x, gfg);

    // 12) routing
    zero_cnt_kernel<<<1, 32>>>();
    route_kernel<<<128, 256>>>(Wg);

    // 13/14) expert FFN — single-pass fp16
    moe_fp16_kernel<1><<<dim3(16, 32, 16), 256>>>(mW1, mb1);
    moe_fp16_kernel<2><<<dim3(16, 8, 16), 256>>>(mW2, mb2);

    // 15) final
    final_kernel<<<4096, 256>>>(out);
}